// round 9
// baseline (speedup 1.0000x reference)
#include <cuda_runtime.h>
#include <cuda_bf16.h>
#include <math.h>
#include <stdint.h>

#define Bc 2
#define Sc 1024
#define Dc 1024
#define Nc 16
#define Hc 64
#define NHc 1024
#define Rc 2048
#define SCALE 0.125f
#define INFV 1000000.0f
#define EPSV 1e-9f
#define PSTR 138

typedef __nv_bfloat16 bf;

// ------------------------- scratch -------------------------
__device__ bf g_in16[4 * 2048 * 1024];
__device__ bf g_w16 [5 * 1024 * 1024];
__device__ bf g_proj[4 * 2048 * 1024];
__device__ bf g_av16[2048 * 1024];
__device__ float g_ao[2048 * 1024];
__device__ float g_rwk[32 * 1024];
__device__ float g_rrt[16 * 2048];
__device__ float g_ttd[2048 * 16 * 2];

// ------------------------- helpers -------------------------
__device__ __forceinline__ uint32_t cvta_s(const void* p){ return (uint32_t)__cvta_generic_to_shared(p); }
__device__ __forceinline__ void cp16(uint32_t d, const void* s){
    asm volatile("cp.async.cg.shared.global [%0], [%1], 16;" :: "r"(d), "l"(s));
}
__device__ __forceinline__ void ldm_x4(uint32_t* r, uint32_t a){
    asm volatile("ldmatrix.sync.aligned.m8n8.x4.shared.b16 {%0,%1,%2,%3}, [%4];"
                 : "=r"(r[0]), "=r"(r[1]), "=r"(r[2]), "=r"(r[3]) : "r"(a));
}
__device__ __forceinline__ void ldm_x4t(uint32_t* r, uint32_t a){
    asm volatile("ldmatrix.sync.aligned.m8n8.x4.trans.shared.b16 {%0,%1,%2,%3}, [%4];"
                 : "=r"(r[0]), "=r"(r[1]), "=r"(r[2]), "=r"(r[3]) : "r"(a));
}
__device__ __forceinline__ void ldm_x2t(uint32_t* r, uint32_t a){
    asm volatile("ldmatrix.sync.aligned.m8n8.x2.trans.shared.b16 {%0,%1}, [%2];"
                 : "=r"(r[0]), "=r"(r[1]) : "r"(a));
}
__device__ __forceinline__ void mma16816(float* d, const uint32_t* a, const uint32_t* b){
    asm volatile("mma.sync.aligned.m16n8k16.row.col.f32.bf16.bf16.f32 "
                 "{%0,%1,%2,%3}, {%4,%5,%6,%7}, {%8,%9}, {%0,%1,%2,%3};"
                 : "+f"(d[0]), "+f"(d[1]), "+f"(d[2]), "+f"(d[3])
                 : "r"(a[0]), "r"(a[1]), "r"(a[2]), "r"(a[3]), "r"(b[0]), "r"(b[1]));
}
__device__ __forceinline__ bf bfc(float x){ return __float2bfloat16(x); }
__device__ __forceinline__ uint32_t pack_bf(float x, float y){
    __nv_bfloat162 h; h.x = __float2bfloat16(x); h.y = __float2bfloat16(y);
    return *reinterpret_cast<uint32_t*>(&h);
}

// ------------------------- merged cast kernel -------------------------
__global__ void castAll_k(const float* __restrict__ a0, const float* __restrict__ a1,
                          const float* __restrict__ a2, const float* __restrict__ a3,
                          const float* __restrict__ w0, const float* __restrict__ w1,
                          const float* __restrict__ w2, const float* __restrict__ w3,
                          const float* __restrict__ w4,
                          bf* __restrict__ outA, bf* __restrict__ outW)
{
    int y = blockIdx.y;
    const float* in; bf* o;
    if (y < 4){
        in = (y == 0) ? a0 : (y == 1) ? a1 : (y == 2) ? a2 : a3;
        o  = outA + (long long)y * 2048 * 1024;
    } else {
        if (blockIdx.x >= 1024) return;
        int yw = y - 4;
        in = (yw == 0) ? w0 : (yw == 1) ? w1 : (yw == 2) ? w2 : (yw == 3) ? w3 : w4;
        o  = outW + (long long)yw * 1024 * 1024;
    }
    long long i4 = ((long long)blockIdx.x * 256 + threadIdx.x) * 4;
    float4 v = *(const float4*)(in + i4);
    __nv_bfloat162 p, q;
    p.x = bfc(v.x); p.y = bfc(v.y); q.x = bfc(v.z); q.y = bfc(v.w);
    *(__nv_bfloat162*)(o + i4)     = p;
    *(__nv_bfloat162*)(o + i4 + 2) = q;
}

// ------------------------- generic bf16 GEMM (proj / outproj) ------------------
template<int BN, int NT_, int EPI>
__global__ __launch_bounds__(256, 2)
void tg(const bf* __restrict__ A, const bf* __restrict__ B,
        const float* __restrict__ bias, const float* __restrict__ bias2,
        float* __restrict__ Cf, bf* __restrict__ Cb,
        int K, int lda, int ldb, int ldc)
{
    constexpr int NS = 4;
    constexpr int ASZ = 128 * 40;
    constexpr int BSTR = BN + 8;
    constexpr int BSZ = 32 * BSTR;
    extern __shared__ __align__(16) bf dyn[];
    bf* Asm = dyn;
    bf* Bsm = dyn + NS * ASZ;

    const int m0 = blockIdx.y * 128;
    int n0 = blockIdx.x * BN;
    const int z = blockIdx.z;
    int zi = 0;
    if (EPI == 6){ zi = z; A += (long long)zi * 2048 * 1024; B += (long long)zi * 1024 * 1024; }

    const int t = threadIdx.x, lane = t & 31, warp = t >> 5, wm = warp >> 2, wn = warp & 3;

    float acc[4][NT_][4];
    #pragma unroll
    for (int a = 0; a < 4; ++a)
        #pragma unroll
        for (int b = 0; b < NT_; ++b)
            #pragma unroll
            for (int c = 0; c < 4; ++c) acc[a][b][c] = 0.f;

    auto loadA = [&](int s, int k0){
        #pragma unroll
        for (int q = 0; q < 2; ++q){
            int c = t * 2 + q, row = c >> 2, seg = c & 3;
            cp16(cvta_s(Asm + s * ASZ + row * 40 + seg * 8),
                 A + (long long)(m0 + row) * lda + k0 + seg * 8);
        }
    };
    auto loadB = [&](int s, int k0){
        constexpr int CPR = BN / 8;
        #pragma unroll
        for (int q = 0; q < (32 * CPR) / 256; ++q){
            int c = t * ((32 * CPR) / 256) + q, row = c / CPR, seg = c % CPR;
            cp16(cvta_s(Bsm + s * BSZ + row * BSTR + seg * 8),
                 B + (long long)(k0 + row) * ldb + n0 + seg * 8);
        }
    };

    const int KT = K / 32;
    loadA(0, 0); loadB(0, 0);
    asm volatile("cp.async.commit_group;");
    if (KT > 1){ loadA(1, 32); loadB(1, 32); }
    asm volatile("cp.async.commit_group;");
    if (KT > 2){ loadA(2, 64); loadB(2, 64); }
    asm volatile("cp.async.commit_group;");

    for (int kt = 0; kt < KT; ++kt){
        asm volatile("cp.async.wait_group 2;");
        __syncthreads();
        int kn = kt + 3;
        if (kn < KT){ loadA(kn & 3, kn * 32); loadB(kn & 3, kn * 32); }
        asm volatile("cp.async.commit_group;");

        const int s = kt & 3;
        const uint32_t aBase = cvta_s(Asm + s * ASZ) + ((wm * 64 + (lane & 15)) * 40) * 2;
        const uint32_t bBase = cvta_s(Bsm + s * BSZ);
        #pragma unroll
        for (int ks = 0; ks < 32; ks += 16){
            uint32_t af[4][4], bfrg[NT_][2];
            #pragma unroll
            for (int mt = 0; mt < 4; ++mt)
                ldm_x4(af[mt], aBase + (mt * 16 * 40 + ks + (lane >> 4) * 8) * 2);
            #pragma unroll
            for (int nt = 0; nt < NT_; ++nt)
                ldm_x2t(bfrg[nt], bBase + (((ks + (lane & 15)) * BSTR + wn * (BN / 4) + nt * 8)) * 2);
            #pragma unroll
            for (int mt = 0; mt < 4; ++mt)
                #pragma unroll
                for (int nt = 0; nt < NT_; ++nt) mma16816(acc[mt][nt], af[mt], bfrg[nt]);
        }
    }

    #pragma unroll
    for (int mt = 0; mt < 4; ++mt)
      #pragma unroll
      for (int r2 = 0; r2 < 2; ++r2){
        const int i = m0 + wm * 64 + mt * 16 + (lane >> 2) + r2 * 8;
        #pragma unroll
        for (int nt = 0; nt < NT_; ++nt)
          #pragma unroll
          for (int c2 = 0; c2 < 2; ++c2){
            const int j = n0 + wn * (BN / 4) + nt * 8 + ((lane & 3) << 1) + c2;
            float v = acc[mt][nt][r2 * 2 + c2];
            if (EPI == 6){
                if (zi == 0) v *= SCALE;
                else if (zi == 1) v += bias[j];
                else if (zi == 2) v += bias2[j];
                Cb[(long long)zi * 2048 * 1024 + (long long)i * 1024 + j] = bfc(v);
            } else { // EPI 4
                Cf[(long long)i * ldc + j] = v + bias[j];
            }
          }
      }
}

// ------------------------- fused flash attention kernel ----------------------
// grid (8 i-tiles, 32 bn). 256 thr, 8 warps, warp = 16 rows.
// rh ring buffer (load 128 new rows/step); score tile processed in two
// 64-column halves to bound register pressure; Pc reads vectorized (PSTR=138).
__global__ __launch_bounds__(256)
void fattn_k(const bf* __restrict__ q16, const bf* __restrict__ k16,
             const bf* __restrict__ v16, const bf* __restrict__ rh16,
             const float* __restrict__ rwkm, const float* __restrict__ rrt,
             const float* __restrict__ ttd, const unsigned char* __restrict__ ttm,
             const float* __restrict__ clsm, bf* __restrict__ av16)
{
    extern __shared__ __align__(16) bf dyn[];
    bf* qs  = dyn;                 // 128*72
    bf* ks  = dyn + 9216;          // 2 x 128*72
    bf* vs  = dyn + 27648;         // 2 x 128*72
    bf* rhs = dyn + 46080;         // 256*72 ring (phys row = t & 255)
    float* Pc = (float*)(dyn + 64512);   // 128 x PSTR fp32

    const int i0 = blockIdx.x * 128;
    const int z  = blockIdx.y, bb = z >> 4, nn = z & 15;
    const int t = threadIdx.x, lane = t & 31, w = t >> 5;
    float* Pw = Pc + w * 16 * PSTR;
    const int tbase = 896 - i0;

    const bf* qg = q16 + ((long long)(bb * 1024 + i0)) * 1024 + nn * 64;

    auto loadKV = [&](int buf, int j0){
        const bf* kg = k16 + ((long long)(bb * 1024 + j0)) * 1024 + nn * 64;
        const bf* vg = v16 + ((long long)(bb * 1024 + j0)) * 1024 + nn * 64;
        #pragma unroll
        for (int qq = 0; qq < 4; ++qq){
            int c = qq * 256 + t, row = c >> 3, seg = c & 7;
            cp16(cvta_s(ks + buf * 9216 + row * 72 + seg * 8), kg + (long long)row * 1024 + seg * 8);
        }
        #pragma unroll
        for (int qq = 0; qq < 4; ++qq){
            int c = qq * 256 + t, row = c >> 3, seg = c & 7;
            cp16(cvta_s(vs + buf * 9216 + row * 72 + seg * 8), vg + (long long)row * 1024 + seg * 8);
        }
    };
    // load 128 rows [t0, t0+128) into the ring
    auto loadRH128 = [&](int t0){
        #pragma unroll
        for (int qq = 0; qq < 4; ++qq){
            int c = qq * 256 + t, row = c >> 3, seg = c & 7;
            int tr = t0 + row;
            cp16(cvta_s(rhs + (tr & 255) * 72 + seg * 8),
                 rh16 + (long long)tr * 1024 + nn * 64 + seg * 8);
        }
    };

    // initial loads: Q, KV(0), RH rows [tbase, tbase+256)
    #pragma unroll
    for (int qq = 0; qq < 4; ++qq){
        int c = qq * 256 + t, row = c >> 3, seg = c & 7;
        cp16(cvta_s(qs + row * 72 + seg * 8), qg + (long long)row * 1024 + seg * 8);
    }
    loadKV(0, 0);
    loadRH128(tbase);
    loadRH128(tbase + 128);
    asm volatile("cp.async.commit_group;");
    asm volatile("cp.async.wait_group 0;");
    __syncthreads();

    const uint32_t aBase = cvta_s(qs) + ((w * 16 + (lane & 15)) * 72 + (lane >> 4) * 8) * 2;
    const uint32_t rBase = cvta_s(rhs);

    uint32_t afq[4][4];
    #pragma unroll
    for (int s = 0; s < 4; ++s) ldm_x4(afq[s], aBase + (s * 16) * 2);

    float accO[8][4];
    #pragma unroll
    for (int a = 0; a < 8; ++a){ accO[a][0] = 0.f; accO[a][1] = 0.f; accO[a][2] = 0.f; accO[a][3] = 0.f; }
    float lsumA = 0.f, lsumB = 0.f;

    const int rl0 = lane >> 2;
    const int iA = i0 + w * 16 + rl0, iB = iA + 8;
    const long long tba = ((long long)(bb * 1024 + iA) * 16 + nn) * 2;
    const long long tbb = ((long long)(bb * 1024 + iB) * 16 + nn) * 2;
    const float tdA0 = ttd[tba], tdA1 = ttd[tba + 1];
    const float tdB0 = ttd[tbb], tdB1 = ttd[tbb + 1];
    const int nt0 = 14 - 2 * w;
    const int bnOff = (lane & 7) + ((lane >> 4) << 3);
    const int bkOff = ((lane >> 3) & 1) << 3;

    for (int jt = 0; jt < 8; ++jt){
        const int j0 = jt * 128;
        const int tb0 = tbase + j0;
        const int buf = jt & 1;
        const float* rrtp = rrt + nn * Rc + tb0;

        if (jt > 0){ asm volatile("cp.async.wait_group 0;"); __syncthreads(); }

        // ---- band-limited pos mma over ring (18 tiles, 3 groups of 6) ----
        #pragma unroll
        for (int g = 0; g < 3; ++g){
            float accP[6][4];
            #pragma unroll
            for (int a = 0; a < 6; ++a){ accP[a][0]=0.f; accP[a][1]=0.f; accP[a][2]=0.f; accP[a][3]=0.f; }
            #pragma unroll
            for (int s = 0; s < 4; ++s){
                #pragma unroll
                for (int u = 0; u < 3; ++u){
                    int ntp = nt0 + g * 6 + u * 2;
                    uint32_t b4[4];
                    ldm_x4(b4, rBase + (((unsigned)(tb0 + ntp * 8 + bnOff) & 255u) * 72 + s * 16 + bkOff) * 2);
                    mma16816(accP[2 * u],     afq[s], b4);
                    mma16816(accP[2 * u + 1], afq[s], b4 + 2);
                }
            }
            #pragma unroll
            for (int u = 0; u < 6; ++u){
                int nt = nt0 + g * 6 + u;
                #pragma unroll
                for (int c = 0; c < 4; ++c){
                    int rl = rl0 + ((c >> 1) << 3);
                    int di = w * 16 + rl;
                    int ct = nt * 8 + ((lane & 3) << 1) + (c & 1);
                    int dj = ct - 128 + di;
                    if (dj >= 0 && dj < 128)
                        Pw[rl * PSTR + dj] = accP[u][c] + rrtp[ct];
                }
            }
        }
        __syncthreads();   // pos reads of ring complete across all warps

        // prefetch next step (overwrites ks/vs[buf^1] and ring slots just freed)
        if (jt < 7){
            loadKV(buf ^ 1, j0 + 128);
            loadRH128(tb0 + 256);
            asm volatile("cp.async.commit_group;");
        }

        const uint32_t kBase = cvta_s(ks + buf * 9216);
        const uint32_t vBase = cvta_s(vs + buf * 9216);
        const float* rwp = rwkm + (long long)z * 1024 + j0;

        // ---- two 64-column halves: content mma -> exp/pack -> PV ----
        #pragma unroll
        for (int hf = 0; hf < 2; ++hf){
            float accC[8][4];
            #pragma unroll
            for (int a = 0; a < 8; ++a){ accC[a][0]=0.f; accC[a][1]=0.f; accC[a][2]=0.f; accC[a][3]=0.f; }
            #pragma unroll
            for (int s = 0; s < 4; ++s){
                #pragma unroll
                for (int np = 0; np < 4; ++np){
                    uint32_t b4[4];
                    ldm_x4(b4, kBase + (((hf * 4 + np) * 16 + bnOff) * 72 + s * 16 + bkOff) * 2);
                    mma16816(accC[2 * np],     afq[s], b4);
                    mma16816(accC[2 * np + 1], afq[s], b4 + 2);
                }
            }

            uint32_t pkA[8], pkB[8];
            #pragma unroll
            for (int nt = 0; nt < 8; ++nt){
                const int djp = hf * 64 + nt * 8 + ((lane & 3) << 1);
                const int jp = j0 + djp;
                float2 rw = *(const float2*)(rwp + djp);
                {
                    float2 cl = *(const float2*)(clsm + (long long)iA * 1024 + jp);
                    uchar2 tm = *(const uchar2*)(ttm + (long long)(bb * 1024 + iA) * 1024 + jp);
                    float2 pp = *(const float2*)(&Pw[rl0 * PSTR + djp]);
                    float e0 = __expf(accC[nt][0] + rw.x + (pp.x + (tm.x ? tdA1 : tdA0)) * cl.x);
                    float e1 = __expf(accC[nt][1] + rw.y + (pp.y + (tm.y ? tdA1 : tdA0)) * cl.y);
                    lsumA += e0 + e1;
                    pkA[nt] = pack_bf(e0, e1);
                }
                {
                    float2 cl = *(const float2*)(clsm + (long long)iB * 1024 + jp);
                    uchar2 tm = *(const uchar2*)(ttm + (long long)(bb * 1024 + iB) * 1024 + jp);
                    float2 pp = *(const float2*)(&Pw[(rl0 + 8) * PSTR + djp]);
                    float e0 = __expf(accC[nt][2] + rw.x + (pp.x + (tm.x ? tdB1 : tdB0)) * cl.x);
                    float e1 = __expf(accC[nt][3] + rw.y + (pp.y + (tm.y ? tdB1 : tdB0)) * cl.y);
                    lsumB += e0 + e1;
                    pkB[nt] = pack_bf(e0, e1);
                }
            }

            #pragma unroll
            for (int u = 0; u < 4; ++u){
                const int kb = hf * 4 + u;
                uint32_t pf[4];
                pf[0] = pkA[2 * u];     pf[1] = pkB[2 * u];
                pf[2] = pkA[2 * u + 1]; pf[3] = pkB[2 * u + 1];
                #pragma unroll
                for (int np = 0; np < 4; ++np){
                    uint32_t b4[4];
                    ldm_x4t(b4, vBase + ((kb * 16 + (lane & 15)) * 72 + np * 16 + (lane >> 4) * 8) * 2);
                    mma16816(accO[2 * np],     pf, b4);
                    mma16816(accO[2 * np + 1], pf, b4 + 2);
                }
            }
        }
    }

    // ---- finalize ----
    lsumA += __shfl_xor_sync(0xffffffffu, lsumA, 1);
    lsumA += __shfl_xor_sync(0xffffffffu, lsumA, 2);
    lsumB += __shfl_xor_sync(0xffffffffu, lsumB, 1);
    lsumB += __shfl_xor_sync(0xffffffffu, lsumB, 2);
    float invA = 1.0f / lsumA, invB = 1.0f / lsumB;
    int rA = bb * 1024 + iA, rB = bb * 1024 + iB;
    #pragma unroll
    for (int nt = 0; nt < 8; ++nt){
        int col = nn * 64 + nt * 8 + ((lane & 3) << 1);
        __nv_bfloat162 p0, p1;
        p0.x = bfc(accO[nt][0] * invA); p0.y = bfc(accO[nt][1] * invA);
        p1.x = bfc(accO[nt][2] * invB); p1.y = bfc(accO[nt][3] * invB);
        *(__nv_bfloat162*)(av16 + (long long)rA * 1024 + col) = p0;
        *(__nv_bfloat162*)(av16 + (long long)rB * 1024 + col) = p1;
    }
}

// ------------------------- merged dot kernels -------------------------
__global__ void dots_k(const bf* __restrict__ q16, const bf* __restrict__ k16,
                       const bf* __restrict__ rh16,
                       const float* __restrict__ rwb, const float* __restrict__ rrb,
                       const float* __restrict__ rsb, const float* __restrict__ seg,
                       const int* __restrict__ amask,
                       float* __restrict__ rwkm, float* __restrict__ rrt, float* __restrict__ ttd)
{
    int gw = (blockIdx.x * blockDim.x + threadIdx.x) >> 5;
    int lane = threadIdx.x & 31;
    if (blockIdx.y == 0){
        int zz = gw >> 10, j = gw & (Sc - 1);
        int b = zz >> 4, n = zz & 15;
        const bf* kp = k16 + ((long long)(b * 1024 + j)) * 1024 + n * 64;
        float d = 0.f;
        #pragma unroll
        for (int h = lane; h < Hc; h += 32) d += rwb[n * Hc + h] * __bfloat162float(kp[h]);
        #pragma unroll
        for (int o = 16; o; o >>= 1) d += __shfl_down_sync(0xffffffffu, d, o);
        if (lane == 0) rwkm[gw] = d * SCALE - INFV * (1.0f - (float)amask[b * Sc + j]);
    } else if (blockIdx.y == 1){
        int n = gw >> 11, tt2 = gw & (Rc - 1);
        const bf* rp = rh16 + (long long)tt2 * 1024 + n * 64;
        float d = 0.f;
        #pragma unroll
        for (int h = lane; h < Hc; h += 32) d += rrb[n * Hc + h] * __bfloat162float(rp[h]);
        #pragma unroll
        for (int o = 16; o; o >>= 1) d += __shfl_down_sync(0xffffffffu, d, o);
        if (lane == 0) rrt[gw] = d * SCALE;
    } else {
        int n = gw & 15;
        long long bi = gw >> 4;
        const bf* qp = q16 + bi * 1024 + n * 64;
        float d0 = 0.f, d1 = 0.f, s0 = 0.f, s1 = 0.f;
        #pragma unroll
        for (int h = lane; h < Hc; h += 32){
            float e0 = seg[n * Hc + h], e1 = seg[Nc * Hc + n * Hc + h];
            float qv = __bfloat162float(qp[h]), rv = rsb[n * Hc + h];
            d0 += qv * e0; d1 += qv * e1; s0 += rv * e0; s1 += rv * e1;
        }
        #pragma unroll
        for (int o = 16; o; o >>= 1){
            d0 += __shfl_down_sync(0xffffffffu, d0, o);
            d1 += __shfl_down_sync(0xffffffffu, d1, o);
            s0 += __shfl_down_sync(0xffffffffu, s0, o);
            s1 += __shfl_down_sync(0xffffffffu, s1, o);
        }
        if (lane == 0){ ttd[2 * gw] = d0 + SCALE * s0; ttd[2 * gw + 1] = d1 + SCALE * s1; }
    }
}

// ------------------------- residual + LayerNorm -------------------------
__global__ void ln_k(const float* __restrict__ query, const float* __restrict__ ao,
                     const float* __restrict__ gamma, const float* __restrict__ beta,
                     float* __restrict__ out){
    __shared__ float red[256];
    long long base = (long long)blockIdx.x * Dc;
    int t = threadIdx.x;
    float x[4]; float s = 0.f;
    #pragma unroll
    for (int u = 0; u < 4; ++u){ x[u] = query[base + t + u * 256] + ao[base + t + u * 256]; s += x[u]; }
    red[t] = s; __syncthreads();
    #pragma unroll
    for (int o = 128; o; o >>= 1){ if (t < o) red[t] += red[t + o]; __syncthreads(); }
    float mu = red[0] * (1.0f / Dc); __syncthreads();
    float s2 = 0.f;
    #pragma unroll
    for (int u = 0; u < 4; ++u){ float d = x[u] - mu; s2 += d * d; }
    red[t] = s2; __syncthreads();
    #pragma unroll
    for (int o = 128; o; o >>= 1){ if (t < o) red[t] += red[t + o]; __syncthreads(); }
    float inv = rsqrtf(red[0] * (1.0f / Dc) + EPSV);
    #pragma unroll
    for (int u = 0; u < 4; ++u){
        int c = t + u * 256;
        out[base + c] = (x[u] - mu) * inv * gamma[c] + beta[c];
    }
}

// ------------------------- driver -------------------------
extern "C" void kernel_launch(void* const* d_in, const int* in_sizes, int n_in,
                              void* d_out, int out_size)
{
    const float* query = (const float*)d_in[0];
    const float* key   = (const float*)d_in[1];
    const float* value = (const float*)d_in[2];
    const float* r     = (const float*)d_in[3];
    const float* clsm  = (const float*)d_in[4];
    const float* Wq    = (const float*)d_in[5];
    const float* Wk    = (const float*)d_in[6];
    const float* bk    = (const float*)d_in[7];
    const float* Wv    = (const float*)d_in[8];
    const float* bv    = (const float*)d_in[9];
    const float* Wo    = (const float*)d_in[10];
    const float* bo    = (const float*)d_in[11];
    const float* rwb   = (const float*)d_in[12];
    const float* rrb   = (const float*)d_in[13];
    const float* rkern = (const float*)d_in[14];
    const float* rsb   = (const float*)d_in[15];
    const float* seg   = (const float*)d_in[16];
    const float* gamma = (const float*)d_in[17];
    const float* beta  = (const float*)d_in[18];
    const unsigned char* ttm = (const unsigned char*)d_in[19];
    const int*   amask = (const int*)d_in[20];
    float* out = (float*)d_out;

    bf *in16, *w16, *proj, *av16;
    float *ao, *rwk, *rrt, *ttd;
    cudaGetSymbolAddress((void**)&in16, g_in16);
    cudaGetSymbolAddress((void**)&w16,  g_w16);
    cudaGetSymbolAddress((void**)&proj, g_proj);
    cudaGetSymbolAddress((void**)&av16, g_av16);
    cudaGetSymbolAddress((void**)&ao,   g_ao);
    cudaGetSymbolAddress((void**)&rwk,  g_rwk);
    cudaGetSymbolAddress((void**)&rrt,  g_rrt);
    cudaGetSymbolAddress((void**)&ttd,  g_ttd);

    bf* q16  = proj;
    bf* k16  = proj + 1LL * 2048 * 1024;
    bf* v16  = proj + 2LL * 2048 * 1024;
    bf* rh16 = proj + 3LL * 2048 * 1024;

    auto k6 = tg<128, 4, 6>;
    auto k4 = tg<128, 4, 4>;
    cudaFuncSetAttribute(k6, cudaFuncAttributeMaxDynamicSharedMemorySize, 75776);
    cudaFuncSetAttribute(k4, cudaFuncAttributeMaxDynamicSharedMemorySize, 75776);
    cudaFuncSetAttribute(fattn_k, cudaFuncAttributeMaxDynamicSharedMemorySize, 199680);

    // 0) casts (merged)
    castAll_k<<<dim3(2048, 9), 256>>>(query, key, value, r, Wq, Wk, Wv, rkern, Wo, in16, w16);

    // 1) merged projections
    k6<<<dim3(8, 16, 4), 256, 75776>>>(in16, w16, bk, bv, nullptr, proj,
        1024, 1024, 1024, 0);

    // 2) merged bias-dot tables (mask folded into rwk)
    dots_k<<<dim3(4096, 3), 256>>>(q16, k16, rh16, rwb, rrb, rsb, seg, amask, rwk, rrt, ttd);

    // 3) fused scores + softmax + PV
    fattn_k<<<dim3(8, 32), 256, 199680>>>(q16, k16, v16, rh16,
        rwk, rrt, ttd, ttm, clsm, av16);

    // 4) output projection + bias
    k4<<<dim3(8, 16, 1), 256, 75776>>>(av16, w16 + 4LL * 1024 * 1024, bo, nullptr, ao, nullptr,
        1024, 1024, 1024, 1024);

    // 5) residual + LayerNorm
    ln_k<<<Bc * Sc, 256>>>(query, ao, gamma, beta, out);

    (void)in_sizes; (void)n_in; (void)out_size;
}

// round 10
// speedup vs baseline: 1.0149x; 1.0149x over previous
#include <cuda_runtime.h>
#include <cuda_bf16.h>
#include <math.h>
#include <stdint.h>

#define Bc 2
#define Sc 1024
#define Dc 1024
#define Nc 16
#define Hc 64
#define NHc 1024
#define Rc 2048
#define SCALE 0.125f
#define INFV 1000000.0f
#define EPSV 1e-9f
#define PSTR 138

typedef __nv_bfloat16 bf;

// ------------------------- scratch -------------------------
__device__ bf g_in16[4 * 2048 * 1024];
__device__ bf g_w16 [5 * 1024 * 1024];
__device__ bf g_proj[4 * 2048 * 1024];
__device__ bf g_av16[2048 * 1024];
__device__ float g_ao[2048 * 1024];
__device__ float g_rwk[32 * 1024];
__device__ float g_rrt[16 * 2048];
__device__ float g_ttd[2048 * 16 * 2];

// ------------------------- helpers -------------------------
__device__ __forceinline__ uint32_t cvta_s(const void* p){ return (uint32_t)__cvta_generic_to_shared(p); }
__device__ __forceinline__ void cp16(uint32_t d, const void* s){
    asm volatile("cp.async.cg.shared.global [%0], [%1], 16;" :: "r"(d), "l"(s));
}
__device__ __forceinline__ void ldm_x4(uint32_t* r, uint32_t a){
    asm volatile("ldmatrix.sync.aligned.m8n8.x4.shared.b16 {%0,%1,%2,%3}, [%4];"
                 : "=r"(r[0]), "=r"(r[1]), "=r"(r[2]), "=r"(r[3]) : "r"(a));
}
__device__ __forceinline__ void ldm_x4t(uint32_t* r, uint32_t a){
    asm volatile("ldmatrix.sync.aligned.m8n8.x4.trans.shared.b16 {%0,%1,%2,%3}, [%4];"
                 : "=r"(r[0]), "=r"(r[1]), "=r"(r[2]), "=r"(r[3]) : "r"(a));
}
__device__ __forceinline__ void ldm_x2t(uint32_t* r, uint32_t a){
    asm volatile("ldmatrix.sync.aligned.m8n8.x2.trans.shared.b16 {%0,%1}, [%2];"
                 : "=r"(r[0]), "=r"(r[1]) : "r"(a));
}
__device__ __forceinline__ void mma16816(float* d, const uint32_t* a, const uint32_t* b){
    asm volatile("mma.sync.aligned.m16n8k16.row.col.f32.bf16.bf16.f32 "
                 "{%0,%1,%2,%3}, {%4,%5,%6,%7}, {%8,%9}, {%0,%1,%2,%3};"
                 : "+f"(d[0]), "+f"(d[1]), "+f"(d[2]), "+f"(d[3])
                 : "r"(a[0]), "r"(a[1]), "r"(a[2]), "r"(a[3]), "r"(b[0]), "r"(b[1]));
}
__device__ __forceinline__ bf bfc(float x){ return __float2bfloat16(x); }
__device__ __forceinline__ uint32_t pack_bf(float x, float y){
    __nv_bfloat162 h; h.x = __float2bfloat16(x); h.y = __float2bfloat16(y);
    return *reinterpret_cast<uint32_t*>(&h);
}

// ------------------------- merged cast kernel -------------------------
__global__ void castAll_k(const float* __restrict__ a0, const float* __restrict__ a1,
                          const float* __restrict__ a2, const float* __restrict__ a3,
                          const float* __restrict__ w0, const float* __restrict__ w1,
                          const float* __restrict__ w2, const float* __restrict__ w3,
                          const float* __restrict__ w4,
                          bf* __restrict__ outA, bf* __restrict__ outW)
{
    int y = blockIdx.y;
    const float* in; bf* o;
    if (y < 4){
        in = (y == 0) ? a0 : (y == 1) ? a1 : (y == 2) ? a2 : a3;
        o  = outA + (long long)y * 2048 * 1024;
    } else {
        if (blockIdx.x >= 1024) return;
        int yw = y - 4;
        in = (yw == 0) ? w0 : (yw == 1) ? w1 : (yw == 2) ? w2 : (yw == 3) ? w3 : w4;
        o  = outW + (long long)yw * 1024 * 1024;
    }
    long long i4 = ((long long)blockIdx.x * 256 + threadIdx.x) * 4;
    float4 v = *(const float4*)(in + i4);
    __nv_bfloat162 p, q;
    p.x = bfc(v.x); p.y = bfc(v.y); q.x = bfc(v.z); q.y = bfc(v.w);
    *(__nv_bfloat162*)(o + i4)     = p;
    *(__nv_bfloat162*)(o + i4 + 2) = q;
}

// ------------------------- generic bf16 GEMM (proj / outproj) ------------------
template<int BN, int NT_, int EPI>
__global__ __launch_bounds__(256, 2)
void tg(const bf* __restrict__ A, const bf* __restrict__ B,
        const float* __restrict__ bias, const float* __restrict__ bias2,
        float* __restrict__ Cf, bf* __restrict__ Cb,
        int K, int lda, int ldb, int ldc)
{
    constexpr int NS = 4;
    constexpr int ASZ = 128 * 40;
    constexpr int BSTR = BN + 8;
    constexpr int BSZ = 32 * BSTR;
    extern __shared__ __align__(16) bf dyn[];
    bf* Asm = dyn;
    bf* Bsm = dyn + NS * ASZ;

    const int m0 = blockIdx.y * 128;
    int n0 = blockIdx.x * BN;
    const int z = blockIdx.z;
    int zi = 0;
    if (EPI == 6){ zi = z; A += (long long)zi * 2048 * 1024; B += (long long)zi * 1024 * 1024; }

    const int t = threadIdx.x, lane = t & 31, warp = t >> 5, wm = warp >> 2, wn = warp & 3;

    float acc[4][NT_][4];
    #pragma unroll
    for (int a = 0; a < 4; ++a)
        #pragma unroll
        for (int b = 0; b < NT_; ++b)
            #pragma unroll
            for (int c = 0; c < 4; ++c) acc[a][b][c] = 0.f;

    auto loadA = [&](int s, int k0){
        #pragma unroll
        for (int q = 0; q < 2; ++q){
            int c = t * 2 + q, row = c >> 2, seg = c & 3;
            cp16(cvta_s(Asm + s * ASZ + row * 40 + seg * 8),
                 A + (long long)(m0 + row) * lda + k0 + seg * 8);
        }
    };
    auto loadB = [&](int s, int k0){
        constexpr int CPR = BN / 8;
        #pragma unroll
        for (int q = 0; q < (32 * CPR) / 256; ++q){
            int c = t * ((32 * CPR) / 256) + q, row = c / CPR, seg = c % CPR;
            cp16(cvta_s(Bsm + s * BSZ + row * BSTR + seg * 8),
                 B + (long long)(k0 + row) * ldb + n0 + seg * 8);
        }
    };

    const int KT = K / 32;
    loadA(0, 0); loadB(0, 0);
    asm volatile("cp.async.commit_group;");
    if (KT > 1){ loadA(1, 32); loadB(1, 32); }
    asm volatile("cp.async.commit_group;");
    if (KT > 2){ loadA(2, 64); loadB(2, 64); }
    asm volatile("cp.async.commit_group;");

    for (int kt = 0; kt < KT; ++kt){
        asm volatile("cp.async.wait_group 2;");
        __syncthreads();
        int kn = kt + 3;
        if (kn < KT){ loadA(kn & 3, kn * 32); loadB(kn & 3, kn * 32); }
        asm volatile("cp.async.commit_group;");

        const int s = kt & 3;
        const uint32_t aBase = cvta_s(Asm + s * ASZ) + ((wm * 64 + (lane & 15)) * 40) * 2;
        const uint32_t bBase = cvta_s(Bsm + s * BSZ);
        #pragma unroll
        for (int ks = 0; ks < 32; ks += 16){
            uint32_t af[4][4], bfrg[NT_][2];
            #pragma unroll
            for (int mt = 0; mt < 4; ++mt)
                ldm_x4(af[mt], aBase + (mt * 16 * 40 + ks + (lane >> 4) * 8) * 2);
            #pragma unroll
            for (int nt = 0; nt < NT_; ++nt)
                ldm_x2t(bfrg[nt], bBase + (((ks + (lane & 15)) * BSTR + wn * (BN / 4) + nt * 8)) * 2);
            #pragma unroll
            for (int mt = 0; mt < 4; ++mt)
                #pragma unroll
                for (int nt = 0; nt < NT_; ++nt) mma16816(acc[mt][nt], af[mt], bfrg[nt]);
        }
    }

    #pragma unroll
    for (int mt = 0; mt < 4; ++mt)
      #pragma unroll
      for (int r2 = 0; r2 < 2; ++r2){
        const int i = m0 + wm * 64 + mt * 16 + (lane >> 2) + r2 * 8;
        #pragma unroll
        for (int nt = 0; nt < NT_; ++nt)
          #pragma unroll
          for (int c2 = 0; c2 < 2; ++c2){
            const int j = n0 + wn * (BN / 4) + nt * 8 + ((lane & 3) << 1) + c2;
            float v = acc[mt][nt][r2 * 2 + c2];
            if (EPI == 6){
                if (zi == 0) v *= SCALE;
                else if (zi == 1) v += bias[j];
                else if (zi == 2) v += bias2[j];
                Cb[(long long)zi * 2048 * 1024 + (long long)i * 1024 + j] = bfc(v);
            } else { // EPI 4
                Cf[(long long)i * ldc + j] = v + bias[j];
            }
          }
      }
}

// ------------------------- fused flash attention kernel ----------------------
// grid (8 i-tiles, 32 bn). 512 thr, 16 warps: wr = w>>1 owns 16 rows,
// hc = w&1 owns a 64-col j-half. Per-warp pos band = 10 tiles with dj-half guard.
// Partial accO/lsum merged through Pc scratch at the end.
__global__ __launch_bounds__(512)
void fattn_k(const bf* __restrict__ q16, const bf* __restrict__ k16,
             const bf* __restrict__ v16, const bf* __restrict__ rh16,
             const float* __restrict__ rwkm, const float* __restrict__ rrt,
             const float* __restrict__ ttd, const unsigned char* __restrict__ ttm,
             const float* __restrict__ clsm, bf* __restrict__ av16)
{
    extern __shared__ __align__(16) bf dyn[];
    bf* qs  = dyn;                 // 128*72
    bf* ks  = dyn + 9216;          // 2 x 128*72
    bf* vs  = dyn + 27648;         // 2 x 128*72
    bf* rhs = dyn + 46080;         // 256*72 (full window, reloaded per step)
    float* Pc = (float*)(dyn + 64512);   // 128 x PSTR fp32 (reused as merge scratch)

    const int i0 = blockIdx.x * 128;
    const int z  = blockIdx.y, bb = z >> 4, nn = z & 15;
    const int t = threadIdx.x, lane = t & 31, w = t >> 5;
    const int wr = w >> 1, hc = w & 1;
    float* Pw = Pc + wr * 16 * PSTR;

    const bf* qg = q16 + ((long long)(bb * 1024 + i0)) * 1024 + nn * 64;

    auto loadKV = [&](int buf, int j0){
        const bf* kg = k16 + ((long long)(bb * 1024 + j0)) * 1024 + nn * 64;
        const bf* vg = v16 + ((long long)(bb * 1024 + j0)) * 1024 + nn * 64;
        #pragma unroll
        for (int qq = 0; qq < 2; ++qq){
            int c = qq * 512 + t, row = c >> 3, seg = c & 7;
            cp16(cvta_s(ks + buf * 9216 + row * 72 + seg * 8), kg + (long long)row * 1024 + seg * 8);
        }
        #pragma unroll
        for (int qq = 0; qq < 2; ++qq){
            int c = qq * 512 + t, row = c >> 3, seg = c & 7;
            cp16(cvta_s(vs + buf * 9216 + row * 72 + seg * 8), vg + (long long)row * 1024 + seg * 8);
        }
    };
    auto loadRH = [&](int tb0){
        const bf* rg = rh16 + (long long)tb0 * 1024 + nn * 64;
        #pragma unroll
        for (int qq = 0; qq < 4; ++qq){
            int c = qq * 512 + t, row = c >> 3, seg = c & 7;
            cp16(cvta_s(rhs + row * 72 + seg * 8), rg + (long long)row * 1024 + seg * 8);
        }
    };

    // initial loads
    #pragma unroll
    for (int qq = 0; qq < 2; ++qq){
        int c = qq * 512 + t, row = c >> 3, seg = c & 7;
        cp16(cvta_s(qs + row * 72 + seg * 8), qg + (long long)row * 1024 + seg * 8);
    }
    loadKV(0, 0);
    loadRH(896 - i0);
    asm volatile("cp.async.commit_group;");
    asm volatile("cp.async.wait_group 0;");
    __syncthreads();

    const uint32_t aBase = cvta_s(qs) + ((wr * 16 + (lane & 15)) * 72 + (lane >> 4) * 8) * 2;
    const uint32_t rBase = cvta_s(rhs);

    uint32_t afq[4][4];
    #pragma unroll
    for (int s = 0; s < 4; ++s) ldm_x4(afq[s], aBase + (s * 16) * 2);

    float accO[8][4];
    #pragma unroll
    for (int a = 0; a < 8; ++a){ accO[a][0] = 0.f; accO[a][1] = 0.f; accO[a][2] = 0.f; accO[a][3] = 0.f; }
    float lsumA = 0.f, lsumB = 0.f;

    const int rl0 = lane >> 2;
    const int iA = i0 + wr * 16 + rl0, iB = iA + 8;
    const long long tba = ((long long)(bb * 1024 + iA) * 16 + nn) * 2;
    const long long tbb = ((long long)(bb * 1024 + iB) * 16 + nn) * 2;
    const float tdA0 = ttd[tba], tdA1 = ttd[tba + 1];
    const float tdB0 = ttd[tbb], tdB1 = ttd[tbb + 1];
    const int nt0 = 14 + 8 * hc - 2 * wr;      // first of 10 band tiles for this warp
    const int djLo = hc * 64;
    const int bnOff = (lane & 7) + ((lane >> 4) << 3);
    const int bkOff = ((lane >> 3) & 1) << 3;

    for (int jt = 0; jt < 8; ++jt){
        const int j0 = jt * 128;
        const int tb0 = 896 + j0 - i0;
        const int buf = jt & 1;
        const float* rrtp = rrt + nn * Rc + tb0;

        if (jt > 0){ asm volatile("cp.async.wait_group 0;"); __syncthreads(); }

        // ---- band-limited pos mma (10 tiles = 5 x4 loads per k-step) ----
        {
            float accP[10][4];
            #pragma unroll
            for (int a = 0; a < 10; ++a){ accP[a][0]=0.f; accP[a][1]=0.f; accP[a][2]=0.f; accP[a][3]=0.f; }
            #pragma unroll
            for (int s = 0; s < 4; ++s){
                #pragma unroll
                for (int u = 0; u < 5; ++u){
                    int ntp = nt0 + 2 * u;
                    uint32_t b4[4];
                    ldm_x4(b4, rBase + ((ntp * 8 + bnOff) * 72 + s * 16 + bkOff) * 2);
                    mma16816(accP[2 * u],     afq[s], b4);
                    mma16816(accP[2 * u + 1], afq[s], b4 + 2);
                }
            }
            #pragma unroll
            for (int u = 0; u < 10; ++u){
                int nt = nt0 + u;
                #pragma unroll
                for (int c = 0; c < 4; ++c){
                    int rl = rl0 + ((c >> 1) << 3);
                    int di = wr * 16 + rl;
                    int ct = nt * 8 + ((lane & 3) << 1) + (c & 1);
                    int dj = ct - 128 + di;
                    if (dj >= djLo && dj < djLo + 64)
                        Pw[rl * PSTR + dj] = accP[u][c] + rrtp[ct];
                }
            }
        }
        __syncwarp();

        // ---- content mma (warp's 64-col half: 8 tiles) ----
        const uint32_t kBase = cvta_s(ks + buf * 9216);
        float accC[8][4];
        #pragma unroll
        for (int a = 0; a < 8; ++a){ accC[a][0]=0.f; accC[a][1]=0.f; accC[a][2]=0.f; accC[a][3]=0.f; }
        #pragma unroll
        for (int s = 0; s < 4; ++s){
            #pragma unroll
            for (int np = 0; np < 4; ++np){
                uint32_t b4[4];
                ldm_x4(b4, kBase + ((djLo + np * 16 + bnOff) * 72 + s * 16 + bkOff) * 2);
                mma16816(accC[2 * np],     afq[s], b4);
                mma16816(accC[2 * np + 1], afq[s], b4 + 2);
            }
        }

        __syncthreads();   // ring+K reads complete across all warps
        if (jt < 7){
            loadKV(buf ^ 1, j0 + 128);
            loadRH(tb0 + 128);
            asm volatile("cp.async.commit_group;");
        }

        // ---- assemble scores, exp, pack ----
        uint32_t pkA[8], pkB[8];
        const float* rwp = rwkm + (long long)z * 1024 + j0;
        #pragma unroll
        for (int nt = 0; nt < 8; ++nt){
            const int djp = djLo + nt * 8 + ((lane & 3) << 1);
            const int jp = j0 + djp;
            float2 rw = *(const float2*)(rwp + djp);
            {
                float2 cl = *(const float2*)(clsm + (long long)iA * 1024 + jp);
                uchar2 tm = *(const uchar2*)(ttm + (long long)(bb * 1024 + iA) * 1024 + jp);
                float2 pp = *(const float2*)(&Pw[rl0 * PSTR + djp]);
                float e0 = __expf(accC[nt][0] + rw.x + (pp.x + (tm.x ? tdA1 : tdA0)) * cl.x);
                float e1 = __expf(accC[nt][1] + rw.y + (pp.y + (tm.y ? tdA1 : tdA0)) * cl.y);
                lsumA += e0 + e1;
                pkA[nt] = pack_bf(e0, e1);
            }
            {
                float2 cl = *(const float2*)(clsm + (long long)iB * 1024 + jp);
                uchar2 tm = *(const uchar2*)(ttm + (long long)(bb * 1024 + iB) * 1024 + jp);
                float2 pp = *(const float2*)(&Pw[(rl0 + 8) * PSTR + djp]);
                float e0 = __expf(accC[nt][2] + rw.x + (pp.x + (tm.x ? tdB1 : tdB0)) * cl.x);
                float e1 = __expf(accC[nt][3] + rw.y + (pp.y + (tm.y ? tdB1 : tdB0)) * cl.y);
                lsumB += e0 + e1;
                pkB[nt] = pack_bf(e0, e1);
            }
        }

        // ---- PV mma over warp's j-half ----
        const uint32_t vBase = cvta_s(vs + buf * 9216);
        #pragma unroll
        for (int u = 0; u < 4; ++u){
            uint32_t pf[4];
            pf[0] = pkA[2 * u];     pf[1] = pkB[2 * u];
            pf[2] = pkA[2 * u + 1]; pf[3] = pkB[2 * u + 1];
            #pragma unroll
            for (int np = 0; np < 4; ++np){
                uint32_t b4[4];
                ldm_x4t(b4, vBase + ((djLo + u * 16 + (lane & 15)) * 72 + np * 16 + (lane >> 4) * 8) * 2);
                mma16816(accO[2 * np],     pf, b4);
                mma16816(accO[2 * np + 1], pf, b4 + 2);
            }
        }
    }

    // ---- merge the two j-half partials through Pc scratch ----
    lsumA += __shfl_xor_sync(0xffffffffu, lsumA, 1);
    lsumA += __shfl_xor_sync(0xffffffffu, lsumA, 2);
    lsumB += __shfl_xor_sync(0xffffffffu, lsumB, 1);
    lsumB += __shfl_xor_sync(0xffffffffu, lsumB, 2);

    float* scr = Pc;
    __syncthreads();               // all Pw reads done before scratch overwrite
    if (hc == 1){
        float* o = scr + wr * 1024 + lane * 32;
        #pragma unroll
        for (int a = 0; a < 8; ++a){
            o[a * 4 + 0] = accO[a][0]; o[a * 4 + 1] = accO[a][1];
            o[a * 4 + 2] = accO[a][2]; o[a * 4 + 3] = accO[a][3];
        }
        if ((lane & 3) == 0){
            scr[8192 + wr * 16 + rl0]     = lsumA;
            scr[8192 + wr * 16 + 8 + rl0] = lsumB;
        }
    }
    __syncthreads();
    if (hc == 0){
        const float* o = scr + wr * 1024 + lane * 32;
        #pragma unroll
        for (int a = 0; a < 8; ++a){
            accO[a][0] += o[a * 4 + 0]; accO[a][1] += o[a * 4 + 1];
            accO[a][2] += o[a * 4 + 2]; accO[a][3] += o[a * 4 + 3];
        }
        lsumA += scr[8192 + wr * 16 + rl0];
        lsumB += scr[8192 + wr * 16 + 8 + rl0];
        float invA = 1.0f / lsumA, invB = 1.0f / lsumB;
        int rA = bb * 1024 + iA, rB = bb * 1024 + iB;
        #pragma unroll
        for (int nt = 0; nt < 8; ++nt){
            int col = nn * 64 + nt * 8 + ((lane & 3) << 1);
            __nv_bfloat162 p0, p1;
            p0.x = bfc(accO[nt][0] * invA); p0.y = bfc(accO[nt][1] * invA);
            p1.x = bfc(accO[nt][2] * invB); p1.y = bfc(accO[nt][3] * invB);
            *(__nv_bfloat162*)(av16 + (long long)rA * 1024 + col) = p0;
            *(__nv_bfloat162*)(av16 + (long long)rB * 1024 + col) = p1;
        }
    }
}

// ------------------------- merged dot kernels -------------------------
__global__ void dots_k(const bf* __restrict__ q16, const bf* __restrict__ k16,
                       const bf* __restrict__ rh16,
                       const float* __restrict__ rwb, const float* __restrict__ rrb,
                       const float* __restrict__ rsb, const float* __restrict__ seg,
                       const int* __restrict__ amask,
                       float* __restrict__ rwkm, float* __restrict__ rrt, float* __restrict__ ttd)
{
    int gw = (blockIdx.x * blockDim.x + threadIdx.x) >> 5;
    int lane = threadIdx.x & 31;
    if (blockIdx.y == 0){
        int zz = gw >> 10, j = gw & (Sc - 1);
        int b = zz >> 4, n = zz & 15;
        const bf* kp = k16 + ((long long)(b * 1024 + j)) * 1024 + n * 64;
        float d = 0.f;
        #pragma unroll
        for (int h = lane; h < Hc; h += 32) d += rwb[n * Hc + h] * __bfloat162float(kp[h]);
        #pragma unroll
        for (int o = 16; o; o >>= 1) d += __shfl_down_sync(0xffffffffu, d, o);
        if (lane == 0) rwkm[gw] = d * SCALE - INFV * (1.0f - (float)amask[b * Sc + j]);
    } else if (blockIdx.y == 1){
        int n = gw >> 11, tt2 = gw & (Rc - 1);
        const bf* rp = rh16 + (long long)tt2 * 1024 + n * 64;
        float d = 0.f;
        #pragma unroll
        for (int h = lane; h < Hc; h += 32) d += rrb[n * Hc + h] * __bfloat162float(rp[h]);
        #pragma unroll
        for (int o = 16; o; o >>= 1) d += __shfl_down_sync(0xffffffffu, d, o);
        if (lane == 0) rrt[gw] = d * SCALE;
    } else {
        int n = gw & 15;
        long long bi = gw >> 4;
        const bf* qp = q16 + bi * 1024 + n * 64;
        float d0 = 0.f, d1 = 0.f, s0 = 0.f, s1 = 0.f;
        #pragma unroll
        for (int h = lane; h < Hc; h += 32){
            float e0 = seg[n * Hc + h], e1 = seg[Nc * Hc + n * Hc + h];
            float qv = __bfloat162float(qp[h]), rv = rsb[n * Hc + h];
            d0 += qv * e0; d1 += qv * e1; s0 += rv * e0; s1 += rv * e1;
        }
        #pragma unroll
        for (int o = 16; o; o >>= 1){
            d0 += __shfl_down_sync(0xffffffffu, d0, o);
            d1 += __shfl_down_sync(0xffffffffu, d1, o);
            s0 += __shfl_down_sync(0xffffffffu, s0, o);
            s1 += __shfl_down_sync(0xffffffffu, s1, o);
        }
        if (lane == 0){ ttd[2 * gw] = d0 + SCALE * s0; ttd[2 * gw + 1] = d1 + SCALE * s1; }
    }
}

// ------------------------- residual + LayerNorm -------------------------
__global__ void ln_k(const float* __restrict__ query, const float* __restrict__ ao,
                     const float* __restrict__ gamma, const float* __restrict__ beta,
                     float* __restrict__ out){
    __shared__ float red[256];
    long long base = (long long)blockIdx.x * Dc;
    int t = threadIdx.x;
    float x[4]; float s = 0.f;
    #pragma unroll
    for (int u = 0; u < 4; ++u){ x[u] = query[base + t + u * 256] + ao[base + t + u * 256]; s += x[u]; }
    red[t] = s; __syncthreads();
    #pragma unroll
    for (int o = 128; o; o >>= 1){ if (t < o) red[t] += red[t + o]; __syncthreads(); }
    float mu = red[0] * (1.0f / Dc); __syncthreads();
    float s2 = 0.f;
    #pragma unroll
    for (int u = 0; u < 4; ++u){ float d = x[u] - mu; s2 += d * d; }
    red[t] = s2; __syncthreads();
    #pragma unroll
    for (int o = 128; o; o >>= 1){ if (t < o) red[t] += red[t + o]; __syncthreads(); }
    float inv = rsqrtf(red[0] * (1.0f / Dc) + EPSV);
    #pragma unroll
    for (int u = 0; u < 4; ++u){
        int c = t + u * 256;
        out[base + c] = (x[u] - mu) * inv * gamma[c] + beta[c];
    }
}

// ------------------------- driver -------------------------
extern "C" void kernel_launch(void* const* d_in, const int* in_sizes, int n_in,
                              void* d_out, int out_size)
{
    const float* query = (const float*)d_in[0];
    const float* key   = (const float*)d_in[1];
    const float* value = (const float*)d_in[2];
    const float* r     = (const float*)d_in[3];
    const float* clsm  = (const float*)d_in[4];
    const float* Wq    = (const float*)d_in[5];
    const float* Wk    = (const float*)d_in[6];
    const float* bk    = (const float*)d_in[7];
    const float* Wv    = (const float*)d_in[8];
    const float* bv    = (const float*)d_in[9];
    const float* Wo    = (const float*)d_in[10];
    const float* bo    = (const float*)d_in[11];
    const float* rwb   = (const float*)d_in[12];
    const float* rrb   = (const float*)d_in[13];
    const float* rkern = (const float*)d_in[14];
    const float* rsb   = (const float*)d_in[15];
    const float* seg   = (const float*)d_in[16];
    const float* gamma = (const float*)d_in[17];
    const float* beta  = (const float*)d_in[18];
    const unsigned char* ttm = (const unsigned char*)d_in[19];
    const int*   amask = (const int*)d_in[20];
    float* out = (float*)d_out;

    bf *in16, *w16, *proj, *av16;
    float *ao, *rwk, *rrt, *ttd;
    cudaGetSymbolAddress((void**)&in16, g_in16);
    cudaGetSymbolAddress((void**)&w16,  g_w16);
    cudaGetSymbolAddress((void**)&proj, g_proj);
    cudaGetSymbolAddress((void**)&av16, g_av16);
    cudaGetSymbolAddress((void**)&ao,   g_ao);
    cudaGetSymbolAddress((void**)&rwk,  g_rwk);
    cudaGetSymbolAddress((void**)&rrt,  g_rrt);
    cudaGetSymbolAddress((void**)&ttd,  g_ttd);

    bf* q16  = proj;
    bf* k16  = proj + 1LL * 2048 * 1024;
    bf* v16  = proj + 2LL * 2048 * 1024;
    bf* rh16 = proj + 3LL * 2048 * 1024;

    auto k6 = tg<128, 4, 6>;
    auto k4 = tg<128, 4, 4>;
    cudaFuncSetAttribute(k6, cudaFuncAttributeMaxDynamicSharedMemorySize, 75776);
    cudaFuncSetAttribute(k4, cudaFuncAttributeMaxDynamicSharedMemorySize, 75776);
    cudaFuncSetAttribute(fattn_k, cudaFuncAttributeMaxDynamicSharedMemorySize, 199680);

    // 0) casts (merged)
    castAll_k<<<dim3(2048, 9), 256>>>(query, key, value, r, Wq, Wk, Wv, rkern, Wo, in16, w16);

    // 1) merged projections
    k6<<<dim3(8, 16, 4), 256, 75776>>>(in16, w16, bk, bv, nullptr, proj,
        1024, 1024, 1024, 0);

    // 2) merged bias-dot tables (mask folded into rwk)
    dots_k<<<dim3(4096, 3), 256>>>(q16, k16, rh16, rwb, rrb, rsb, seg, amask, rwk, rrt, ttd);

    // 3) fused scores + softmax + PV (512 threads, 16 warps)
    fattn_k<<<dim3(8, 32), 512, 199680>>>(q16, k16, v16, rh16,
        rwk, rrt, ttd, ttm, clsm, av16);

    // 4) output projection + bias
    k4<<<dim3(8, 16, 1), 256, 75776>>>(av16, w16 + 4LL * 1024 * 1024, bo, nullptr, ao, nullptr,
        1024, 1024, 1024, 1024);

    // 5) residual + LayerNorm
    ln_k<<<Bc * Sc, 256>>>(query, ao, gamma, beta, out);

    (void)in_sizes; (void)n_in; (void)out_size;
}

// round 11
// speedup vs baseline: 1.0608x; 1.0452x over previous
#include <cuda_runtime.h>
#include <cuda_bf16.h>
#include <math.h>
#include <stdint.h>

#define Bc 2
#define Sc 1024
#define Dc 1024
#define Nc 16
#define Hc 64
#define NHc 1024
#define Rc 2048
#define SCALE 0.125f
#define INFV 1000000.0f
#define EPSV 1e-9f
#define PSTR 138

typedef __nv_bfloat16 bf;

// ------------------------- scratch -------------------------
__device__ bf g_in16[4 * 2048 * 1024];
__device__ bf g_w16 [5 * 1024 * 1024];
__device__ bf g_proj[4 * 2048 * 1024];
__device__ bf g_av16[2048 * 1024];
__device__ float g_ao[2048 * 1024];
__device__ float g_rwk[32 * 1024];
__device__ float g_rrt[16 * 2048];
__device__ float g_ttd[2048 * 16 * 2];

// ------------------------- helpers -------------------------
__device__ __forceinline__ uint32_t cvta_s(const void* p){ return (uint32_t)__cvta_generic_to_shared(p); }
__device__ __forceinline__ void cp16(uint32_t d, const void* s){
    asm volatile("cp.async.cg.shared.global [%0], [%1], 16;" :: "r"(d), "l"(s));
}
__device__ __forceinline__ void ldm_x4(uint32_t* r, uint32_t a){
    asm volatile("ldmatrix.sync.aligned.m8n8.x4.shared.b16 {%0,%1,%2,%3}, [%4];"
                 : "=r"(r[0]), "=r"(r[1]), "=r"(r[2]), "=r"(r[3]) : "r"(a));
}
__device__ __forceinline__ void ldm_x4t(uint32_t* r, uint32_t a){
    asm volatile("ldmatrix.sync.aligned.m8n8.x4.trans.shared.b16 {%0,%1,%2,%3}, [%4];"
                 : "=r"(r[0]), "=r"(r[1]), "=r"(r[2]), "=r"(r[3]) : "r"(a));
}
__device__ __forceinline__ void ldm_x2t(uint32_t* r, uint32_t a){
    asm volatile("ldmatrix.sync.aligned.m8n8.x2.trans.shared.b16 {%0,%1}, [%2];"
                 : "=r"(r[0]), "=r"(r[1]) : "r"(a));
}
__device__ __forceinline__ void mma16816(float* d, const uint32_t* a, const uint32_t* b){
    asm volatile("mma.sync.aligned.m16n8k16.row.col.f32.bf16.bf16.f32 "
                 "{%0,%1,%2,%3}, {%4,%5,%6,%7}, {%8,%9}, {%0,%1,%2,%3};"
                 : "+f"(d[0]), "+f"(d[1]), "+f"(d[2]), "+f"(d[3])
                 : "r"(a[0]), "r"(a[1]), "r"(a[2]), "r"(a[3]), "r"(b[0]), "r"(b[1]));
}
__device__ __forceinline__ bf bfc(float x){ return __float2bfloat16(x); }
__device__ __forceinline__ uint32_t pack_bf(float x, float y){
    __nv_bfloat162 h; h.x = __float2bfloat16(x); h.y = __float2bfloat16(y);
    return *reinterpret_cast<uint32_t*>(&h);
}

// ------------------------- merged cast kernel -------------------------
__global__ void castAll_k(const float* __restrict__ a0, const float* __restrict__ a1,
                          const float* __restrict__ a2, const float* __restrict__ a3,
                          const float* __restrict__ w0, const float* __restrict__ w1,
                          const float* __restrict__ w2, const float* __restrict__ w3,
                          const float* __restrict__ w4,
                          bf* __restrict__ outA, bf* __restrict__ outW)
{
    int y = blockIdx.y;
    const float* in; bf* o;
    if (y < 4){
        in = (y == 0) ? a0 : (y == 1) ? a1 : (y == 2) ? a2 : a3;
        o  = outA + (long long)y * 2048 * 1024;
    } else {
        if (blockIdx.x >= 1024) return;
        int yw = y - 4;
        in = (yw == 0) ? w0 : (yw == 1) ? w1 : (yw == 2) ? w2 : (yw == 3) ? w3 : w4;
        o  = outW + (long long)yw * 1024 * 1024;
    }
    long long i4 = ((long long)blockIdx.x * 256 + threadIdx.x) * 4;
    float4 v = *(const float4*)(in + i4);
    __nv_bfloat162 p, q;
    p.x = bfc(v.x); p.y = bfc(v.y); q.x = bfc(v.z); q.y = bfc(v.w);
    *(__nv_bfloat162*)(o + i4)     = p;
    *(__nv_bfloat162*)(o + i4 + 2) = q;
}

// ------------------------- generic bf16 GEMM (proj / outproj) ------------------
template<int BN, int NT_, int EPI>
__global__ __launch_bounds__(256, 2)
void tg(const bf* __restrict__ A, const bf* __restrict__ B,
        const float* __restrict__ bias, const float* __restrict__ bias2,
        float* __restrict__ Cf, bf* __restrict__ Cb,
        int K, int lda, int ldb, int ldc)
{
    constexpr int NS = 4;
    constexpr int ASZ = 128 * 40;
    constexpr int BSTR = BN + 8;
    constexpr int BSZ = 32 * BSTR;
    extern __shared__ __align__(16) bf dyn[];
    bf* Asm = dyn;
    bf* Bsm = dyn + NS * ASZ;

    const int m0 = blockIdx.y * 128;
    int n0 = blockIdx.x * BN;
    const int z = blockIdx.z;
    int zi = 0;
    if (EPI == 6){ zi = z; A += (long long)zi * 2048 * 1024; B += (long long)zi * 1024 * 1024; }

    const int t = threadIdx.x, lane = t & 31, warp = t >> 5, wm = warp >> 2, wn = warp & 3;

    float acc[4][NT_][4];
    #pragma unroll
    for (int a = 0; a < 4; ++a)
        #pragma unroll
        for (int b = 0; b < NT_; ++b)
            #pragma unroll
            for (int c = 0; c < 4; ++c) acc[a][b][c] = 0.f;

    auto loadA = [&](int s, int k0){
        #pragma unroll
        for (int q = 0; q < 2; ++q){
            int c = t * 2 + q, row = c >> 2, seg = c & 3;
            cp16(cvta_s(Asm + s * ASZ + row * 40 + seg * 8),
                 A + (long long)(m0 + row) * lda + k0 + seg * 8);
        }
    };
    auto loadB = [&](int s, int k0){
        constexpr int CPR = BN / 8;
        #pragma unroll
        for (int q = 0; q < (32 * CPR) / 256; ++q){
            int c = t * ((32 * CPR) / 256) + q, row = c / CPR, seg = c % CPR;
            cp16(cvta_s(Bsm + s * BSZ + row * BSTR + seg * 8),
                 B + (long long)(k0 + row) * ldb + n0 + seg * 8);
        }
    };

    const int KT = K / 32;
    loadA(0, 0); loadB(0, 0);
    asm volatile("cp.async.commit_group;");
    if (KT > 1){ loadA(1, 32); loadB(1, 32); }
    asm volatile("cp.async.commit_group;");
    if (KT > 2){ loadA(2, 64); loadB(2, 64); }
    asm volatile("cp.async.commit_group;");

    for (int kt = 0; kt < KT; ++kt){
        asm volatile("cp.async.wait_group 2;");
        __syncthreads();
        int kn = kt + 3;
        if (kn < KT){ loadA(kn & 3, kn * 32); loadB(kn & 3, kn * 32); }
        asm volatile("cp.async.commit_group;");

        const int s = kt & 3;
        const uint32_t aBase = cvta_s(Asm + s * ASZ) + ((wm * 64 + (lane & 15)) * 40) * 2;
        const uint32_t bBase = cvta_s(Bsm + s * BSZ);
        #pragma unroll
        for (int ks = 0; ks < 32; ks += 16){
            uint32_t af[4][4], bfrg[NT_][2];
            #pragma unroll
            for (int mt = 0; mt < 4; ++mt)
                ldm_x4(af[mt], aBase + (mt * 16 * 40 + ks + (lane >> 4) * 8) * 2);
            #pragma unroll
            for (int nt = 0; nt < NT_; ++nt)
                ldm_x2t(bfrg[nt], bBase + (((ks + (lane & 15)) * BSTR + wn * (BN / 4) + nt * 8)) * 2);
            #pragma unroll
            for (int mt = 0; mt < 4; ++mt)
                #pragma unroll
                for (int nt = 0; nt < NT_; ++nt) mma16816(acc[mt][nt], af[mt], bfrg[nt]);
        }
    }

    #pragma unroll
    for (int mt = 0; mt < 4; ++mt)
      #pragma unroll
      for (int r2 = 0; r2 < 2; ++r2){
        const int i = m0 + wm * 64 + mt * 16 + (lane >> 2) + r2 * 8;
        #pragma unroll
        for (int nt = 0; nt < NT_; ++nt)
          #pragma unroll
          for (int c2 = 0; c2 < 2; ++c2){
            const int j = n0 + wn * (BN / 4) + nt * 8 + ((lane & 3) << 1) + c2;
            float v = acc[mt][nt][r2 * 2 + c2];
            if (EPI == 6){
                if (zi == 0) v *= SCALE;
                else if (zi == 1) v += bias[j];
                else if (zi == 2) v += bias2[j];
                Cb[(long long)zi * 2048 * 1024 + (long long)i * 1024 + j] = bfc(v);
            } else { // EPI 4
                Cf[(long long)i * ldc + j] = v + bias[j];
            }
          }
      }
}

// ------------------------- fused flash attention kernel ----------------------
// R8 dataflow (8 warps, full-width accC) + rh ring buffer + split prefetch +
// vectorized Pc reads (PSTR=138).
__global__ __launch_bounds__(256)
void fattn_k(const bf* __restrict__ q16, const bf* __restrict__ k16,
             const bf* __restrict__ v16, const bf* __restrict__ rh16,
             const float* __restrict__ rwkm, const float* __restrict__ rrt,
             const float* __restrict__ ttd, const unsigned char* __restrict__ ttm,
             const float* __restrict__ clsm, bf* __restrict__ av16)
{
    extern __shared__ __align__(16) bf dyn[];
    bf* qs  = dyn;                 // 128*72
    bf* ks  = dyn + 9216;          // 2 x 128*72
    bf* vs  = dyn + 27648;         // 2 x 128*72
    bf* rhs = dyn + 46080;         // 256*72 ring (phys row = r & 255)
    float* Pc = (float*)(dyn + 64512);   // 128 x PSTR fp32

    const int i0 = blockIdx.x * 128;
    const int z  = blockIdx.y, bb = z >> 4, nn = z & 15;
    const int t = threadIdx.x, lane = t & 31, w = t >> 5;
    float* Pw = Pc + w * 16 * PSTR;
    const int tbase = 896 - i0;

    const bf* qg = q16 + ((long long)(bb * 1024 + i0)) * 1024 + nn * 64;

    auto loadKV = [&](int buf, int j0){
        const bf* kg = k16 + ((long long)(bb * 1024 + j0)) * 1024 + nn * 64;
        const bf* vg = v16 + ((long long)(bb * 1024 + j0)) * 1024 + nn * 64;
        #pragma unroll
        for (int qq = 0; qq < 4; ++qq){
            int c = qq * 256 + t, row = c >> 3, seg = c & 7;
            cp16(cvta_s(ks + buf * 9216 + row * 72 + seg * 8), kg + (long long)row * 1024 + seg * 8);
        }
        #pragma unroll
        for (int qq = 0; qq < 4; ++qq){
            int c = qq * 256 + t, row = c >> 3, seg = c & 7;
            cp16(cvta_s(vs + buf * 9216 + row * 72 + seg * 8), vg + (long long)row * 1024 + seg * 8);
        }
    };
    // load 128 rows [t0, t0+128) into the ring
    auto loadRH128 = [&](int t0){
        #pragma unroll
        for (int qq = 0; qq < 4; ++qq){
            int c = qq * 256 + t, row = c >> 3, seg = c & 7;
            int tr = t0 + row;
            cp16(cvta_s(rhs + (tr & 255) * 72 + seg * 8),
                 rh16 + (long long)tr * 1024 + nn * 64 + seg * 8);
        }
    };

    // initial loads: Q, KV(0), RH rows [tbase, tbase+256)
    #pragma unroll
    for (int qq = 0; qq < 4; ++qq){
        int c = qq * 256 + t, row = c >> 3, seg = c & 7;
        cp16(cvta_s(qs + row * 72 + seg * 8), qg + (long long)row * 1024 + seg * 8);
    }
    loadKV(0, 0);
    loadRH128(tbase);
    loadRH128(tbase + 128);
    asm volatile("cp.async.commit_group;");
    asm volatile("cp.async.wait_group 0;");
    __syncthreads();

    const uint32_t aBase = cvta_s(qs) + ((w * 16 + (lane & 15)) * 72 + (lane >> 4) * 8) * 2;
    const uint32_t rBase = cvta_s(rhs);

    uint32_t afq[4][4];
    #pragma unroll
    for (int s = 0; s < 4; ++s) ldm_x4(afq[s], aBase + (s * 16) * 2);

    float accO[8][4];
    #pragma unroll
    for (int a = 0; a < 8; ++a){ accO[a][0] = 0.f; accO[a][1] = 0.f; accO[a][2] = 0.f; accO[a][3] = 0.f; }
    float lsumA = 0.f, lsumB = 0.f;

    const int rl0 = lane >> 2;
    const int iA = i0 + w * 16 + rl0, iB = iA + 8;
    const long long tba = ((long long)(bb * 1024 + iA) * 16 + nn) * 2;
    const long long tbb = ((long long)(bb * 1024 + iB) * 16 + nn) * 2;
    const float tdA0 = ttd[tba], tdA1 = ttd[tba + 1];
    const float tdB0 = ttd[tbb], tdB1 = ttd[tbb + 1];
    const int nt0 = 14 - 2 * w;
    const int bnOff = (lane & 7) + ((lane >> 4) << 3);
    const int bkOff = ((lane >> 3) & 1) << 3;

    for (int jt = 0; jt < 8; ++jt){
        const int j0 = jt * 128;
        const int tb0 = tbase + j0;
        const int buf = jt & 1;
        const float* rrtp = rrt + nn * Rc + tb0;

        if (jt > 0){ asm volatile("cp.async.wait_group 0;"); __syncthreads(); }

        // KV prefetch for next step — buf^1 fully consumed last iter (loop-top sync)
        if (jt < 7){
            loadKV(buf ^ 1, j0 + 128);
            asm volatile("cp.async.commit_group;");
        }

        // ---- band-limited pos mma over ring (18 tiles, 3 groups of 6) ----
        #pragma unroll
        for (int g = 0; g < 3; ++g){
            float accP[6][4];
            #pragma unroll
            for (int a = 0; a < 6; ++a){ accP[a][0]=0.f; accP[a][1]=0.f; accP[a][2]=0.f; accP[a][3]=0.f; }
            #pragma unroll
            for (int s = 0; s < 4; ++s){
                #pragma unroll
                for (int u = 0; u < 3; ++u){
                    int ntp = nt0 + g * 6 + u * 2;
                    uint32_t b4[4];
                    ldm_x4(b4, rBase + (((unsigned)(tb0 + ntp * 8 + bnOff) & 255u) * 72 + s * 16 + bkOff) * 2);
                    mma16816(accP[2 * u],     afq[s], b4);
                    mma16816(accP[2 * u + 1], afq[s], b4 + 2);
                }
            }
            #pragma unroll
            for (int u = 0; u < 6; ++u){
                int nt = nt0 + g * 6 + u;
                #pragma unroll
                for (int c = 0; c < 4; ++c){
                    int rl = rl0 + ((c >> 1) << 3);
                    int di = w * 16 + rl;
                    int ct = nt * 8 + ((lane & 3) << 1) + (c & 1);
                    int dj = ct - 128 + di;
                    if (dj >= 0 && dj < 128)
                        Pw[rl * PSTR + dj] = accP[u][c] + rrtp[ct];
                }
            }
        }
        __syncwarp();

        // ---- content mma (16 tiles via x4 loads) ----
        const uint32_t kBase = cvta_s(ks + buf * 9216);
        float accC[16][4];
        #pragma unroll
        for (int a = 0; a < 16; ++a){ accC[a][0]=0.f; accC[a][1]=0.f; accC[a][2]=0.f; accC[a][3]=0.f; }
        #pragma unroll
        for (int s = 0; s < 4; ++s){
            #pragma unroll
            for (int np = 0; np < 8; ++np){
                uint32_t b4[4];
                ldm_x4(b4, kBase + ((np * 16 + bnOff) * 72 + s * 16 + bkOff) * 2);
                mma16816(accC[2 * np],     afq[s], b4);
                mma16816(accC[2 * np + 1], afq[s], b4 + 2);
            }
        }

        __syncthreads();   // all warps done with ring + ks[buf] mma reads
        // rh ring prefetch — overwrites slots [tb0, tb0+128) just freed
        if (jt < 7){
            loadRH128(tb0 + 256);
            asm volatile("cp.async.commit_group;");
        }

        // ---- assemble scores, exp, pack (no max pass) ----
        uint32_t pkA[16], pkB[16];
        const float* rwp = rwkm + (long long)z * 1024 + j0;
        #pragma unroll
        for (int nt = 0; nt < 16; ++nt){
            const int djp = nt * 8 + ((lane & 3) << 1);
            const int jp = j0 + djp;
            float2 rw = *(const float2*)(rwp + djp);
            {
                float2 cl = *(const float2*)(clsm + (long long)iA * 1024 + jp);
                uchar2 tm = *(const uchar2*)(ttm + (long long)(bb * 1024 + iA) * 1024 + jp);
                float2 pp = *(const float2*)(&Pw[rl0 * PSTR + djp]);
                float e0 = __expf(accC[nt][0] + rw.x + (pp.x + (tm.x ? tdA1 : tdA0)) * cl.x);
                float e1 = __expf(accC[nt][1] + rw.y + (pp.y + (tm.y ? tdA1 : tdA0)) * cl.y);
                lsumA += e0 + e1;
                pkA[nt] = pack_bf(e0, e1);
            }
            {
                float2 cl = *(const float2*)(clsm + (long long)iB * 1024 + jp);
                uchar2 tm = *(const uchar2*)(ttm + (long long)(bb * 1024 + iB) * 1024 + jp);
                float2 pp = *(const float2*)(&Pw[(rl0 + 8) * PSTR + djp]);
                float e0 = __expf(accC[nt][2] + rw.x + (pp.x + (tm.x ? tdB1 : tdB0)) * cl.x);
                float e1 = __expf(accC[nt][3] + rw.y + (pp.y + (tm.y ? tdB1 : tdB0)) * cl.y);
                lsumB += e0 + e1;
                pkB[nt] = pack_bf(e0, e1);
            }
        }

        // ---- PV mma: accO += P @ V (x4.trans loads) ----
        const uint32_t vBase = cvta_s(vs + buf * 9216);
        #pragma unroll
        for (int kb = 0; kb < 8; ++kb){
            uint32_t pf[4];
            pf[0] = pkA[2 * kb];     pf[1] = pkB[2 * kb];
            pf[2] = pkA[2 * kb + 1]; pf[3] = pkB[2 * kb + 1];
            #pragma unroll
            for (int np = 0; np < 4; ++np){
                uint32_t b4[4];
                ldm_x4t(b4, vBase + ((kb * 16 + (lane & 15)) * 72 + np * 16 + (lane >> 4) * 8) * 2);
                mma16816(accO[2 * np],     pf, b4);
                mma16816(accO[2 * np + 1], pf, b4 + 2);
            }
        }
    }

    // ---- finalize ----
    lsumA += __shfl_xor_sync(0xffffffffu, lsumA, 1);
    lsumA += __shfl_xor_sync(0xffffffffu, lsumA, 2);
    lsumB += __shfl_xor_sync(0xffffffffu, lsumB, 1);
    lsumB += __shfl_xor_sync(0xffffffffu, lsumB, 2);
    float invA = 1.0f / lsumA, invB = 1.0f / lsumB;
    int rA = bb * 1024 + iA, rB = bb * 1024 + iB;
    #pragma unroll
    for (int nt = 0; nt < 8; ++nt){
        int col = nn * 64 + nt * 8 + ((lane & 3) << 1);
        __nv_bfloat162 p0, p1;
        p0.x = bfc(accO[nt][0] * invA); p0.y = bfc(accO[nt][1] * invA);
        p1.x = bfc(accO[nt][2] * invB); p1.y = bfc(accO[nt][3] * invB);
        *(__nv_bfloat162*)(av16 + (long long)rA * 1024 + col) = p0;
        *(__nv_bfloat162*)(av16 + (long long)rB * 1024 + col) = p1;
    }
}

// ------------------------- merged dot kernels -------------------------
__global__ void dots_k(const bf* __restrict__ q16, const bf* __restrict__ k16,
                       const bf* __restrict__ rh16,
                       const float* __restrict__ rwb, const float* __restrict__ rrb,
                       const float* __restrict__ rsb, const float* __restrict__ seg,
                       const int* __restrict__ amask,
                       float* __restrict__ rwkm, float* __restrict__ rrt, float* __restrict__ ttd)
{
    int gw = (blockIdx.x * blockDim.x + threadIdx.x) >> 5;
    int lane = threadIdx.x & 31;
    if (blockIdx.y == 0){
        int zz = gw >> 10, j = gw & (Sc - 1);
        int b = zz >> 4, n = zz & 15;
        const bf* kp = k16 + ((long long)(b * 1024 + j)) * 1024 + n * 64;
        float d = 0.f;
        #pragma unroll
        for (int h = lane; h < Hc; h += 32) d += rwb[n * Hc + h] * __bfloat162float(kp[h]);
        #pragma unroll
        for (int o = 16; o; o >>= 1) d += __shfl_down_sync(0xffffffffu, d, o);
        if (lane == 0) rwkm[gw] = d * SCALE - INFV * (1.0f - (float)amask[b * Sc + j]);
    } else if (blockIdx.y == 1){
        int n = gw >> 11, tt2 = gw & (Rc - 1);
        const bf* rp = rh16 + (long long)tt2 * 1024 + n * 64;
        float d = 0.f;
        #pragma unroll
        for (int h = lane; h < Hc; h += 32) d += rrb[n * Hc + h] * __bfloat162float(rp[h]);
        #pragma unroll
        for (int o = 16; o; o >>= 1) d += __shfl_down_sync(0xffffffffu, d, o);
        if (lane == 0) rrt[gw] = d * SCALE;
    } else {
        int n = gw & 15;
        long long bi = gw >> 4;
        const bf* qp = q16 + bi * 1024 + n * 64;
        float d0 = 0.f, d1 = 0.f, s0 = 0.f, s1 = 0.f;
        #pragma unroll
        for (int h = lane; h < Hc; h += 32){
            float e0 = seg[n * Hc + h], e1 = seg[Nc * Hc + n * Hc + h];
            float qv = __bfloat162float(qp[h]), rv = rsb[n * Hc + h];
            d0 += qv * e0; d1 += qv * e1; s0 += rv * e0; s1 += rv * e1;
        }
        #pragma unroll
        for (int o = 16; o; o >>= 1){
            d0 += __shfl_down_sync(0xffffffffu, d0, o);
            d1 += __shfl_down_sync(0xffffffffu, d1, o);
            s0 += __shfl_down_sync(0xffffffffu, s0, o);
            s1 += __shfl_down_sync(0xffffffffu, s1, o);
        }
        if (lane == 0){ ttd[2 * gw] = d0 + SCALE * s0; ttd[2 * gw + 1] = d1 + SCALE * s1; }
    }
}

// ------------------------- residual + LayerNorm -------------------------
__global__ void ln_k(const float* __restrict__ query, const float* __restrict__ ao,
                     const float* __restrict__ gamma, const float* __restrict__ beta,
                     float* __restrict__ out){
    __shared__ float red[256];
    long long base = (long long)blockIdx.x * Dc;
    int t = threadIdx.x;
    float x[4]; float s = 0.f;
    #pragma unroll
    for (int u = 0; u < 4; ++u){ x[u] = query[base + t + u * 256] + ao[base + t + u * 256]; s += x[u]; }
    red[t] = s; __syncthreads();
    #pragma unroll
    for (int o = 128; o; o >>= 1){ if (t < o) red[t] += red[t + o]; __syncthreads(); }
    float mu = red[0] * (1.0f / Dc); __syncthreads();
    float s2 = 0.f;
    #pragma unroll
    for (int u = 0; u < 4; ++u){ float d = x[u] - mu; s2 += d * d; }
    red[t] = s2; __syncthreads();
    #pragma unroll
    for (int o = 128; o; o >>= 1){ if (t < o) red[t] += red[t + o]; __syncthreads(); }
    float inv = rsqrtf(red[0] * (1.0f / Dc) + EPSV);
    #pragma unroll
    for (int u = 0; u < 4; ++u){
        int c = t + u * 256;
        out[base + c] = (x[u] - mu) * inv * gamma[c] + beta[c];
    }
}

// ------------------------- driver -------------------------
extern "C" void kernel_launch(void* const* d_in, const int* in_sizes, int n_in,
                              void* d_out, int out_size)
{
    const float* query = (const float*)d_in[0];
    const float* key   = (const float*)d_in[1];
    const float* value = (const float*)d_in[2];
    const float* r     = (const float*)d_in[3];
    const float* clsm  = (const float*)d_in[4];
    const float* Wq    = (const float*)d_in[5];
    const float* Wk    = (const float*)d_in[6];
    const float* bk    = (const float*)d_in[7];
    const float* Wv    = (const float*)d_in[8];
    const float* bv    = (const float*)d_in[9];
    const float* Wo    = (const float*)d_in[10];
    const float* bo    = (const float*)d_in[11];
    const float* rwb   = (const float*)d_in[12];
    const float* rrb   = (const float*)d_in[13];
    const float* rkern = (const float*)d_in[14];
    const float* rsb   = (const float*)d_in[15];
    const float* seg   = (const float*)d_in[16];
    const float* gamma = (const float*)d_in[17];
    const float* beta  = (const float*)d_in[18];
    const unsigned char* ttm = (const unsigned char*)d_in[19];
    const int*   amask = (const int*)d_in[20];
    float* out = (float*)d_out;

    bf *in16, *w16, *proj, *av16;
    float *ao, *rwk, *rrt, *ttd;
    cudaGetSymbolAddress((void**)&in16, g_in16);
    cudaGetSymbolAddress((void**)&w16,  g_w16);
    cudaGetSymbolAddress((void**)&proj, g_proj);
    cudaGetSymbolAddress((void**)&av16, g_av16);
    cudaGetSymbolAddress((void**)&ao,   g_ao);
    cudaGetSymbolAddress((void**)&rwk,  g_rwk);
    cudaGetSymbolAddress((void**)&rrt,  g_rrt);
    cudaGetSymbolAddress((void**)&ttd,  g_ttd);

    bf* q16  = proj;
    bf* k16  = proj + 1LL * 2048 * 1024;
    bf* v16  = proj + 2LL * 2048 * 1024;
    bf* rh16 = proj + 3LL * 2048 * 1024;

    auto k6 = tg<128, 4, 6>;
    auto k4 = tg<128, 4, 4>;
    cudaFuncSetAttribute(k6, cudaFuncAttributeMaxDynamicSharedMemorySize, 75776);
    cudaFuncSetAttribute(k4, cudaFuncAttributeMaxDynamicSharedMemorySize, 75776);
    cudaFuncSetAttribute(fattn_k, cudaFuncAttributeMaxDynamicSharedMemorySize, 199680);

    // 0) casts (merged)
    castAll_k<<<dim3(2048, 9), 256>>>(query, key, value, r, Wq, Wk, Wv, rkern, Wo, in16, w16);

    // 1) merged projections
    k6<<<dim3(8, 16, 4), 256, 75776>>>(in16, w16, bk, bv, nullptr, proj,
        1024, 1024, 1024, 0);

    // 2) merged bias-dot tables (mask folded into rwk)
    dots_k<<<dim3(4096, 3), 256>>>(q16, k16, rh16, rwb, rrb, rsb, seg, amask, rwk, rrt, ttd);

    // 3) fused scores + softmax + PV
    fattn_k<<<dim3(8, 32), 256, 199680>>>(q16, k16, v16, rh16,
        rwk, rrt, ttd, ttm, clsm, av16);

    // 4) output projection + bias
    k4<<<dim3(8, 16, 1), 256, 75776>>>(av16, w16 + 4LL * 1024 * 1024, bo, nullptr, ao, nullptr,
        1024, 1024, 1024, 1024);

    // 5) residual + LayerNorm
    ln_k<<<Bc * Sc, 256>>>(query, ao, gamma, beta, out);

    (void)in_sizes; (void)n_in; (void)out_size;
}

// round 12
// speedup vs baseline: 1.1334x; 1.0685x over previous
#include <cuda_runtime.h>
#include <cuda_bf16.h>
#include <math.h>
#include <stdint.h>

#define Bc 2
#define Sc 1024
#define Dc 1024
#define Nc 16
#define Hc 64
#define NHc 1024
#define Rc 2048
#define SCALE 0.125f
#define INFV 1000000.0f
#define EPSV 1e-9f
#define PSTRB 136

typedef __nv_bfloat16 bf;

// ------------------------- scratch -------------------------
__device__ bf g_in16[4 * 2048 * 1024];
__device__ bf g_w16 [5 * 1024 * 1024];
__device__ bf g_proj[4 * 2048 * 1024];
__device__ bf g_av16[2048 * 1024];
__device__ float g_ao[2048 * 1024];
__device__ float g_rwk[32 * 1024];
__device__ float g_rrt[16 * 2048];
__device__ float g_ttd[2048 * 16 * 2];
__device__ unsigned char g_comb[2 * 1024 * 1024];   // ttm | (clsm!=0)<<1

// ------------------------- helpers -------------------------
__device__ __forceinline__ uint32_t cvta_s(const void* p){ return (uint32_t)__cvta_generic_to_shared(p); }
__device__ __forceinline__ void cp16(uint32_t d, const void* s){
    asm volatile("cp.async.cg.shared.global [%0], [%1], 16;" :: "r"(d), "l"(s));
}
__device__ __forceinline__ void ldm_x4(uint32_t* r, uint32_t a){
    asm volatile("ldmatrix.sync.aligned.m8n8.x4.shared.b16 {%0,%1,%2,%3}, [%4];"
                 : "=r"(r[0]), "=r"(r[1]), "=r"(r[2]), "=r"(r[3]) : "r"(a));
}
__device__ __forceinline__ void ldm_x4t(uint32_t* r, uint32_t a){
    asm volatile("ldmatrix.sync.aligned.m8n8.x4.trans.shared.b16 {%0,%1,%2,%3}, [%4];"
                 : "=r"(r[0]), "=r"(r[1]), "=r"(r[2]), "=r"(r[3]) : "r"(a));
}
__device__ __forceinline__ void ldm_x2t(uint32_t* r, uint32_t a){
    asm volatile("ldmatrix.sync.aligned.m8n8.x2.trans.shared.b16 {%0,%1}, [%2];"
                 : "=r"(r[0]), "=r"(r[1]) : "r"(a));
}
__device__ __forceinline__ void mma16816(float* d, const uint32_t* a, const uint32_t* b){
    asm volatile("mma.sync.aligned.m16n8k16.row.col.f32.bf16.bf16.f32 "
                 "{%0,%1,%2,%3}, {%4,%5,%6,%7}, {%8,%9}, {%0,%1,%2,%3};"
                 : "+f"(d[0]), "+f"(d[1]), "+f"(d[2]), "+f"(d[3])
                 : "r"(a[0]), "r"(a[1]), "r"(a[2]), "r"(a[3]), "r"(b[0]), "r"(b[1]));
}
__device__ __forceinline__ bf bfc(float x){ return __float2bfloat16(x); }
__device__ __forceinline__ uint32_t pack_bf(float x, float y){
    __nv_bfloat162 h; h.x = __float2bfloat16(x); h.y = __float2bfloat16(y);
    return *reinterpret_cast<uint32_t*>(&h);
}

// ------------------------- merged cast kernel -------------------------
// y 0..3: A inputs; 4..8: weights; 9: comb = ttm | (clsm!=0)<<1
__global__ void castAll_k(const float* __restrict__ a0, const float* __restrict__ a1,
                          const float* __restrict__ a2, const float* __restrict__ a3,
                          const float* __restrict__ w0, const float* __restrict__ w1,
                          const float* __restrict__ w2, const float* __restrict__ w3,
                          const float* __restrict__ w4,
                          const unsigned char* __restrict__ ttm, const float* __restrict__ clsm,
                          bf* __restrict__ outA, bf* __restrict__ outW,
                          unsigned char* __restrict__ comb)
{
    int y = blockIdx.y;
    long long i4 = ((long long)blockIdx.x * 256 + threadIdx.x) * 4;
    if (y == 9){
        uchar4 tm = *(const uchar4*)(ttm + i4);
        float4 cl = *(const float4*)(clsm + (i4 & 0xFFFFF));
        uchar4 o;
        o.x = (tm.x ? 1 : 0) | (cl.x != 0.f ? 2 : 0);
        o.y = (tm.y ? 1 : 0) | (cl.y != 0.f ? 2 : 0);
        o.z = (tm.z ? 1 : 0) | (cl.z != 0.f ? 2 : 0);
        o.w = (tm.w ? 1 : 0) | (cl.w != 0.f ? 2 : 0);
        *(uchar4*)(comb + i4) = o;
        return;
    }
    const float* in; bf* o;
    if (y < 4){
        in = (y == 0) ? a0 : (y == 1) ? a1 : (y == 2) ? a2 : a3;
        o  = outA + (long long)y * 2048 * 1024;
    } else {
        if (blockIdx.x >= 1024) return;
        int yw = y - 4;
        in = (yw == 0) ? w0 : (yw == 1) ? w1 : (yw == 2) ? w2 : (yw == 3) ? w3 : w4;
        o  = outW + (long long)yw * 1024 * 1024;
    }
    float4 v = *(const float4*)(in + i4);
    __nv_bfloat162 p, q;
    p.x = bfc(v.x); p.y = bfc(v.y); q.x = bfc(v.z); q.y = bfc(v.w);
    *(__nv_bfloat162*)(o + i4)     = p;
    *(__nv_bfloat162*)(o + i4 + 2) = q;
}

// ------------------------- generic bf16 GEMM (proj / outproj) ------------------
template<int BN, int NT_, int EPI>
__global__ __launch_bounds__(256, 2)
void tg(const bf* __restrict__ A, const bf* __restrict__ B,
        const float* __restrict__ bias, const float* __restrict__ bias2,
        float* __restrict__ Cf, bf* __restrict__ Cb,
        int K, int lda, int ldb, int ldc)
{
    constexpr int NS = 4;
    constexpr int ASZ = 128 * 40;
    constexpr int BSTR = BN + 8;
    constexpr int BSZ = 32 * BSTR;
    extern __shared__ __align__(16) bf dyn[];
    bf* Asm = dyn;
    bf* Bsm = dyn + NS * ASZ;

    const int m0 = blockIdx.y * 128;
    int n0 = blockIdx.x * BN;
    const int z = blockIdx.z;
    int zi = 0;
    if (EPI == 6){ zi = z; A += (long long)zi * 2048 * 1024; B += (long long)zi * 1024 * 1024; }

    const int t = threadIdx.x, lane = t & 31, warp = t >> 5, wm = warp >> 2, wn = warp & 3;

    float acc[4][NT_][4];
    #pragma unroll
    for (int a = 0; a < 4; ++a)
        #pragma unroll
        for (int b = 0; b < NT_; ++b)
            #pragma unroll
            for (int c = 0; c < 4; ++c) acc[a][b][c] = 0.f;

    auto loadA = [&](int s, int k0){
        #pragma unroll
        for (int q = 0; q < 2; ++q){
            int c = t * 2 + q, row = c >> 2, seg = c & 3;
            cp16(cvta_s(Asm + s * ASZ + row * 40 + seg * 8),
                 A + (long long)(m0 + row) * lda + k0 + seg * 8);
        }
    };
    auto loadB = [&](int s, int k0){
        constexpr int CPR = BN / 8;
        #pragma unroll
        for (int q = 0; q < (32 * CPR) / 256; ++q){
            int c = t * ((32 * CPR) / 256) + q, row = c / CPR, seg = c % CPR;
            cp16(cvta_s(Bsm + s * BSZ + row * BSTR + seg * 8),
                 B + (long long)(k0 + row) * ldb + n0 + seg * 8);
        }
    };

    const int KT = K / 32;
    loadA(0, 0); loadB(0, 0);
    asm volatile("cp.async.commit_group;");
    if (KT > 1){ loadA(1, 32); loadB(1, 32); }
    asm volatile("cp.async.commit_group;");
    if (KT > 2){ loadA(2, 64); loadB(2, 64); }
    asm volatile("cp.async.commit_group;");

    for (int kt = 0; kt < KT; ++kt){
        asm volatile("cp.async.wait_group 2;");
        __syncthreads();
        int kn = kt + 3;
        if (kn < KT){ loadA(kn & 3, kn * 32); loadB(kn & 3, kn * 32); }
        asm volatile("cp.async.commit_group;");

        const int s = kt & 3;
        const uint32_t aBase = cvta_s(Asm + s * ASZ) + ((wm * 64 + (lane & 15)) * 40) * 2;
        const uint32_t bBase = cvta_s(Bsm + s * BSZ);
        #pragma unroll
        for (int ks = 0; ks < 32; ks += 16){
            uint32_t af[4][4], bfrg[NT_][2];
            #pragma unroll
            for (int mt = 0; mt < 4; ++mt)
                ldm_x4(af[mt], aBase + (mt * 16 * 40 + ks + (lane >> 4) * 8) * 2);
            #pragma unroll
            for (int nt = 0; nt < NT_; ++nt)
                ldm_x2t(bfrg[nt], bBase + (((ks + (lane & 15)) * BSTR + wn * (BN / 4) + nt * 8)) * 2);
            #pragma unroll
            for (int mt = 0; mt < 4; ++mt)
                #pragma unroll
                for (int nt = 0; nt < NT_; ++nt) mma16816(acc[mt][nt], af[mt], bfrg[nt]);
        }
    }

    #pragma unroll
    for (int mt = 0; mt < 4; ++mt)
      #pragma unroll
      for (int r2 = 0; r2 < 2; ++r2){
        const int i = m0 + wm * 64 + mt * 16 + (lane >> 2) + r2 * 8;
        #pragma unroll
        for (int nt = 0; nt < NT_; ++nt)
          #pragma unroll
          for (int c2 = 0; c2 < 2; ++c2){
            const int j = n0 + wn * (BN / 4) + nt * 8 + ((lane & 3) << 1) + c2;
            float v = acc[mt][nt][r2 * 2 + c2];
            if (EPI == 6){
                if (zi == 0) v *= SCALE;
                else if (zi == 1) v += bias[j];
                else if (zi == 2) v += bias2[j];
                Cb[(long long)zi * 2048 * 1024 + (long long)i * 1024 + j] = bfc(v);
            } else { // EPI 4
                Cf[(long long)i * ldc + j] = v + bias[j];
            }
          }
      }
}

// ------------------------- fused flash attention kernel ----------------------
// R11 structure + comb uint8 (clsm+ttm fused) + Pc in bf16 (PSTRB=136).
__global__ __launch_bounds__(256)
void fattn_k(const bf* __restrict__ q16, const bf* __restrict__ k16,
             const bf* __restrict__ v16, const bf* __restrict__ rh16,
             const float* __restrict__ rwkm, const float* __restrict__ rrt,
             const float* __restrict__ ttd, const unsigned char* __restrict__ comb,
             bf* __restrict__ av16)
{
    extern __shared__ __align__(16) bf dyn[];
    bf* qs  = dyn;                 // 128*72
    bf* ks  = dyn + 9216;          // 2 x 128*72
    bf* vs  = dyn + 27648;         // 2 x 128*72
    bf* rhs = dyn + 46080;         // 256*72 ring (phys row = r & 255)
    bf* Pcb = dyn + 64512;         // 128 x PSTRB bf16

    const int i0 = blockIdx.x * 128;
    const int z  = blockIdx.y, bb = z >> 4, nn = z & 15;
    const int t = threadIdx.x, lane = t & 31, w = t >> 5;
    bf* Pw = Pcb + w * 16 * PSTRB;
    const int tbase = 896 - i0;

    const bf* qg = q16 + ((long long)(bb * 1024 + i0)) * 1024 + nn * 64;

    auto loadKV = [&](int buf, int j0){
        const bf* kg = k16 + ((long long)(bb * 1024 + j0)) * 1024 + nn * 64;
        const bf* vg = v16 + ((long long)(bb * 1024 + j0)) * 1024 + nn * 64;
        #pragma unroll
        for (int qq = 0; qq < 4; ++qq){
            int c = qq * 256 + t, row = c >> 3, seg = c & 7;
            cp16(cvta_s(ks + buf * 9216 + row * 72 + seg * 8), kg + (long long)row * 1024 + seg * 8);
        }
        #pragma unroll
        for (int qq = 0; qq < 4; ++qq){
            int c = qq * 256 + t, row = c >> 3, seg = c & 7;
            cp16(cvta_s(vs + buf * 9216 + row * 72 + seg * 8), vg + (long long)row * 1024 + seg * 8);
        }
    };
    auto loadRH128 = [&](int t0){
        #pragma unroll
        for (int qq = 0; qq < 4; ++qq){
            int c = qq * 256 + t, row = c >> 3, seg = c & 7;
            int tr = t0 + row;
            cp16(cvta_s(rhs + (tr & 255) * 72 + seg * 8),
                 rh16 + (long long)tr * 1024 + nn * 64 + seg * 8);
        }
    };

    #pragma unroll
    for (int qq = 0; qq < 4; ++qq){
        int c = qq * 256 + t, row = c >> 3, seg = c & 7;
        cp16(cvta_s(qs + row * 72 + seg * 8), qg + (long long)row * 1024 + seg * 8);
    }
    loadKV(0, 0);
    loadRH128(tbase);
    loadRH128(tbase + 128);
    asm volatile("cp.async.commit_group;");
    asm volatile("cp.async.wait_group 0;");
    __syncthreads();

    const uint32_t aBase = cvta_s(qs) + ((w * 16 + (lane & 15)) * 72 + (lane >> 4) * 8) * 2;
    const uint32_t rBase = cvta_s(rhs);

    uint32_t afq[4][4];
    #pragma unroll
    for (int s = 0; s < 4; ++s) ldm_x4(afq[s], aBase + (s * 16) * 2);

    float accO[8][4];
    #pragma unroll
    for (int a = 0; a < 8; ++a){ accO[a][0] = 0.f; accO[a][1] = 0.f; accO[a][2] = 0.f; accO[a][3] = 0.f; }
    float lsumA = 0.f, lsumB = 0.f;

    const int rl0 = lane >> 2;
    const int iA = i0 + w * 16 + rl0, iB = iA + 8;
    const long long tba = ((long long)(bb * 1024 + iA) * 16 + nn) * 2;
    const long long tbb = ((long long)(bb * 1024 + iB) * 16 + nn) * 2;
    const float tdA0 = ttd[tba], tdA1 = ttd[tba + 1];
    const float tdB0 = ttd[tbb], tdB1 = ttd[tbb + 1];
    const int nt0 = 14 - 2 * w;
    const int bnOff = (lane & 7) + ((lane >> 4) << 3);
    const int bkOff = ((lane >> 3) & 1) << 3;

    for (int jt = 0; jt < 8; ++jt){
        const int j0 = jt * 128;
        const int tb0 = tbase + j0;
        const int buf = jt & 1;
        const float* rrtp = rrt + nn * Rc + tb0;

        if (jt > 0){ asm volatile("cp.async.wait_group 0;"); __syncthreads(); }

        if (jt < 7){
            loadKV(buf ^ 1, j0 + 128);
            asm volatile("cp.async.commit_group;");
        }

        // ---- band-limited pos mma over ring (18 tiles, 3 groups of 6) ----
        #pragma unroll
        for (int g = 0; g < 3; ++g){
            float accP[6][4];
            #pragma unroll
            for (int a = 0; a < 6; ++a){ accP[a][0]=0.f; accP[a][1]=0.f; accP[a][2]=0.f; accP[a][3]=0.f; }
            #pragma unroll
            for (int s = 0; s < 4; ++s){
                #pragma unroll
                for (int u = 0; u < 3; ++u){
                    int ntp = nt0 + g * 6 + u * 2;
                    uint32_t b4[4];
                    ldm_x4(b4, rBase + (((unsigned)(tb0 + ntp * 8 + bnOff) & 255u) * 72 + s * 16 + bkOff) * 2);
                    mma16816(accP[2 * u],     afq[s], b4);
                    mma16816(accP[2 * u + 1], afq[s], b4 + 2);
                }
            }
            #pragma unroll
            for (int u = 0; u < 6; ++u){
                int nt = nt0 + g * 6 + u;
                #pragma unroll
                for (int c = 0; c < 4; ++c){
                    int rl = rl0 + ((c >> 1) << 3);
                    int di = w * 16 + rl;
                    int ct = nt * 8 + ((lane & 3) << 1) + (c & 1);
                    int dj = ct - 128 + di;
                    if (dj >= 0 && dj < 128)
                        Pw[rl * PSTRB + dj] = bfc(accP[u][c] + rrtp[ct]);
                }
            }
        }
        __syncwarp();

        // ---- content mma (16 tiles via x4 loads) ----
        const uint32_t kBase = cvta_s(ks + buf * 9216);
        float accC[16][4];
        #pragma unroll
        for (int a = 0; a < 16; ++a){ accC[a][0]=0.f; accC[a][1]=0.f; accC[a][2]=0.f; accC[a][3]=0.f; }
        #pragma unroll
        for (int s = 0; s < 4; ++s){
            #pragma unroll
            for (int np = 0; np < 8; ++np){
                uint32_t b4[4];
                ldm_x4(b4, kBase + ((np * 16 + bnOff) * 72 + s * 16 + bkOff) * 2);
                mma16816(accC[2 * np],     afq[s], b4);
                mma16816(accC[2 * np + 1], afq[s], b4 + 2);
            }
        }

        __syncthreads();
        if (jt < 7){
            loadRH128(tb0 + 256);
            asm volatile("cp.async.commit_group;");
        }

        // ---- assemble scores, exp, pack ----
        uint32_t pkA[16], pkB[16];
        const float* rwp = rwkm + (long long)z * 1024 + j0;
        const unsigned char* cmA = comb + (long long)(bb * 1024 + iA) * 1024 + j0;
        const unsigned char* cmB = comb + (long long)(bb * 1024 + iB) * 1024 + j0;
        #pragma unroll
        for (int nt = 0; nt < 16; ++nt){
            const int djp = nt * 8 + ((lane & 3) << 1);
            float2 rw = *(const float2*)(rwp + djp);
            {
                uchar2 cm = *(const uchar2*)(cmA + djp);
                __nv_bfloat162 pb = *(const __nv_bfloat162*)(&Pw[rl0 * PSTRB + djp]);
                float clx = (cm.x & 2) ? 1.f : 0.f, cly = (cm.y & 2) ? 1.f : 0.f;
                float t0 = (cm.x & 1) ? tdA1 : tdA0, t1 = (cm.y & 1) ? tdA1 : tdA0;
                float e0 = __expf(accC[nt][0] + rw.x + (__bfloat162float(pb.x) + t0) * clx);
                float e1 = __expf(accC[nt][1] + rw.y + (__bfloat162float(pb.y) + t1) * cly);
                lsumA += e0 + e1;
                pkA[nt] = pack_bf(e0, e1);
            }
            {
                uchar2 cm = *(const uchar2*)(cmB + djp);
                __nv_bfloat162 pb = *(const __nv_bfloat162*)(&Pw[(rl0 + 8) * PSTRB + djp]);
                float clx = (cm.x & 2) ? 1.f : 0.f, cly = (cm.y & 2) ? 1.f : 0.f;
                float t0 = (cm.x & 1) ? tdB1 : tdB0, t1 = (cm.y & 1) ? tdB1 : tdB0;
                float e0 = __expf(accC[nt][2] + rw.x + (__bfloat162float(pb.x) + t0) * clx);
                float e1 = __expf(accC[nt][3] + rw.y + (__bfloat162float(pb.y) + t1) * cly);
                lsumB += e0 + e1;
                pkB[nt] = pack_bf(e0, e1);
            }
        }

        // ---- PV mma ----
        const uint32_t vBase = cvta_s(vs + buf * 9216);
        #pragma unroll
        for (int kb = 0; kb < 8; ++kb){
            uint32_t pf[4];
            pf[0] = pkA[2 * kb];     pf[1] = pkB[2 * kb];
            pf[2] = pkA[2 * kb + 1]; pf[3] = pkB[2 * kb + 1];
            #pragma unroll
            for (int np = 0; np < 4; ++np){
                uint32_t b4[4];
                ldm_x4t(b4, vBase + ((kb * 16 + (lane & 15)) * 72 + np * 16 + (lane >> 4) * 8) * 2);
                mma16816(accO[2 * np],     pf, b4);
                mma16816(accO[2 * np + 1], pf, b4 + 2);
            }
        }
    }

    // ---- finalize ----
    lsumA += __shfl_xor_sync(0xffffffffu, lsumA, 1);
    lsumA += __shfl_xor_sync(0xffffffffu, lsumA, 2);
    lsumB += __shfl_xor_sync(0xffffffffu, lsumB, 1);
    lsumB += __shfl_xor_sync(0xffffffffu, lsumB, 2);
    float invA = 1.0f / lsumA, invB = 1.0f / lsumB;
    int rA = bb * 1024 + iA, rB = bb * 1024 + iB;
    #pragma unroll
    for (int nt = 0; nt < 8; ++nt){
        int col = nn * 64 + nt * 8 + ((lane & 3) << 1);
        __nv_bfloat162 p0, p1;
        p0.x = bfc(accO[nt][0] * invA); p0.y = bfc(accO[nt][1] * invA);
        p1.x = bfc(accO[nt][2] * invB); p1.y = bfc(accO[nt][3] * invB);
        *(__nv_bfloat162*)(av16 + (long long)rA * 1024 + col) = p0;
        *(__nv_bfloat162*)(av16 + (long long)rB * 1024 + col) = p1;
    }
}

// ------------------------- merged dot kernels -------------------------
__global__ void dots_k(const bf* __restrict__ q16, const bf* __restrict__ k16,
                       const bf* __restrict__ rh16,
                       const float* __restrict__ rwb, const float* __restrict__ rrb,
                       const float* __restrict__ rsb, const float* __restrict__ seg,
                       const int* __restrict__ amask,
                       float* __restrict__ rwkm, float* __restrict__ rrt, float* __restrict__ ttd)
{
    int gw = (blockIdx.x * blockDim.x + threadIdx.x) >> 5;
    int lane = threadIdx.x & 31;
    if (blockIdx.y == 0){
        int zz = gw >> 10, j = gw & (Sc - 1);
        int b = zz >> 4, n = zz & 15;
        const bf* kp = k16 + ((long long)(b * 1024 + j)) * 1024 + n * 64;
        float d = 0.f;
        #pragma unroll
        for (int h = lane; h < Hc; h += 32) d += rwb[n * Hc + h] * __bfloat162float(kp[h]);
        #pragma unroll
        for (int o = 16; o; o >>= 1) d += __shfl_down_sync(0xffffffffu, d, o);
        if (lane == 0) rwkm[gw] = d * SCALE - INFV * (1.0f - (float)amask[b * Sc + j]);
    } else if (blockIdx.y == 1){
        int n = gw >> 11, tt2 = gw & (Rc - 1);
        const bf* rp = rh16 + (long long)tt2 * 1024 + n * 64;
        float d = 0.f;
        #pragma unroll
        for (int h = lane; h < Hc; h += 32) d += rrb[n * Hc + h] * __bfloat162float(rp[h]);
        #pragma unroll
        for (int o = 16; o; o >>= 1) d += __shfl_down_sync(0xffffffffu, d, o);
        if (lane == 0) rrt[gw] = d * SCALE;
    } else {
        int n = gw & 15;
        long long bi = gw >> 4;
        const bf* qp = q16 + bi * 1024 + n * 64;
        float d0 = 0.f, d1 = 0.f, s0 = 0.f, s1 = 0.f;
        #pragma unroll
        for (int h = lane; h < Hc; h += 32){
            float e0 = seg[n * Hc + h], e1 = seg[Nc * Hc + n * Hc + h];
            float qv = __bfloat162float(qp[h]), rv = rsb[n * Hc + h];
            d0 += qv * e0; d1 += qv * e1; s0 += rv * e0; s1 += rv * e1;
        }
        #pragma unroll
        for (int o = 16; o; o >>= 1){
            d0 += __shfl_down_sync(0xffffffffu, d0, o);
            d1 += __shfl_down_sync(0xffffffffu, d1, o);
            s0 += __shfl_down_sync(0xffffffffu, s0, o);
            s1 += __shfl_down_sync(0xffffffffu, s1, o);
        }
        if (lane == 0){ ttd[2 * gw] = d0 + SCALE * s0; ttd[2 * gw + 1] = d1 + SCALE * s1; }
    }
}

// ------------------------- residual + LayerNorm -------------------------
__global__ void ln_k(const float* __restrict__ query, const float* __restrict__ ao,
                     const float* __restrict__ gamma, const float* __restrict__ beta,
                     float* __restrict__ out){
    __shared__ float red[256];
    long long base = (long long)blockIdx.x * Dc;
    int t = threadIdx.x;
    float x[4]; float s = 0.f;
    #pragma unroll
    for (int u = 0; u < 4; ++u){ x[u] = query[base + t + u * 256] + ao[base + t + u * 256]; s += x[u]; }
    red[t] = s; __syncthreads();
    #pragma unroll
    for (int o = 128; o; o >>= 1){ if (t < o) red[t] += red[t + o]; __syncthreads(); }
    float mu = red[0] * (1.0f / Dc); __syncthreads();
    float s2 = 0.f;
    #pragma unroll
    for (int u = 0; u < 4; ++u){ float d = x[u] - mu; s2 += d * d; }
    red[t] = s2; __syncthreads();
    #pragma unroll
    for (int o = 128; o; o >>= 1){ if (t < o) red[t] += red[t + o]; __syncthreads(); }
    float inv = rsqrtf(red[0] * (1.0f / Dc) + EPSV);
    #pragma unroll
    for (int u = 0; u < 4; ++u){
        int c = t + u * 256;
        out[base + c] = (x[u] - mu) * inv * gamma[c] + beta[c];
    }
}

// ------------------------- driver -------------------------
extern "C" void kernel_launch(void* const* d_in, const int* in_sizes, int n_in,
                              void* d_out, int out_size)
{
    const float* query = (const float*)d_in[0];
    const float* key   = (const float*)d_in[1];
    const float* value = (const float*)d_in[2];
    const float* r     = (const float*)d_in[3];
    const float* clsm  = (const float*)d_in[4];
    const float* Wq    = (const float*)d_in[5];
    const float* Wk    = (const float*)d_in[6];
    const float* bk    = (const float*)d_in[7];
    const float* Wv    = (const float*)d_in[8];
    const float* bv    = (const float*)d_in[9];
    const float* Wo    = (const float*)d_in[10];
    const float* bo    = (const float*)d_in[11];
    const float* rwb   = (const float*)d_in[12];
    const float* rrb   = (const float*)d_in[13];
    const float* rkern = (const float*)d_in[14];
    const float* rsb   = (const float*)d_in[15];
    const float* seg   = (const float*)d_in[16];
    const float* gamma = (const float*)d_in[17];
    const float* beta  = (const float*)d_in[18];
    const unsigned char* ttm = (const unsigned char*)d_in[19];
    const int*   amask = (const int*)d_in[20];
    float* out = (float*)d_out;

    bf *in16, *w16, *proj, *av16;
    float *ao, *rwk, *rrt, *ttd;
    unsigned char* comb;
    cudaGetSymbolAddress((void**)&in16, g_in16);
    cudaGetSymbolAddress((void**)&w16,  g_w16);
    cudaGetSymbolAddress((void**)&proj, g_proj);
    cudaGetSymbolAddress((void**)&av16, g_av16);
    cudaGetSymbolAddress((void**)&ao,   g_ao);
    cudaGetSymbolAddress((void**)&rwk,  g_rwk);
    cudaGetSymbolAddress((void**)&rrt,  g_rrt);
    cudaGetSymbolAddress((void**)&ttd,  g_ttd);
    cudaGetSymbolAddress((void**)&comb, g_comb);

    bf* q16  = proj;
    bf* k16  = proj + 1LL * 2048 * 1024;
    bf* v16  = proj + 2LL * 2048 * 1024;
    bf* rh16 = proj + 3LL * 2048 * 1024;

    auto k6 = tg<128, 4, 6>;
    auto k4 = tg<128, 4, 4>;
    cudaFuncSetAttribute(k6, cudaFuncAttributeMaxDynamicSharedMemorySize, 75776);
    cudaFuncSetAttribute(k4, cudaFuncAttributeMaxDynamicSharedMemorySize, 75776);
    cudaFuncSetAttribute(fattn_k, cudaFuncAttributeMaxDynamicSharedMemorySize, 163840);

    // 0) casts + comb (merged)
    castAll_k<<<dim3(2048, 10), 256>>>(query, key, value, r, Wq, Wk, Wv, rkern, Wo,
                                       ttm, clsm, in16, w16, comb);

    // 1) merged projections
    k6<<<dim3(8, 16, 4), 256, 75776>>>(in16, w16, bk, bv, nullptr, proj,
        1024, 1024, 1024, 0);

    // 2) merged bias-dot tables (mask folded into rwk)
    dots_k<<<dim3(4096, 3), 256>>>(q16, k16, rh16, rwb, rrb, rsb, seg, amask, rwk, rrt, ttd);

    // 3) fused scores + softmax + PV
    fattn_k<<<dim3(8, 32), 256, 163840>>>(q16, k16, v16, rh16,
        rwk, rrt, ttd, comb, av16);

    // 4) output projection + bias
    k4<<<dim3(8, 16, 1), 256, 75776>>>(av16, w16 + 4LL * 1024 * 1024, bo, nullptr, ao, nullptr,
        1024, 1024, 1024, 1024);

    // 5) residual + LayerNorm
    ln_k<<<Bc * Sc, 256>>>(query, ao, gamma, beta, out);

    (void)in_sizes; (void)n_in; (void)out_size;
}